// round 2
// baseline (speedup 1.0000x reference)
#include <cuda_runtime.h>
#include <math.h>

#define B_  2
#define T_  2048
#define E_  1024
#define H_  16
#define HD_ 64
#define M_  (B_*T_)   // 4096
#define NT_ (T_/64)   // 32

// ---------------- scratch (static device globals; no allocation) ----------------
__device__ float g_Q[B_*H_*T_*HD_];     // [B,H,T,HD]
__device__ float g_K[B_*H_*T_*HD_];
__device__ float g_V[B_*H_*T_*HD_];
__device__ float g_G[B_*T_*E_];         // silu(gate)  [B,T,E]
__device__ float g_O[B_*T_*E_];         // attention out [B,T,E]
__device__ float g_GN[B_*T_*E_];        // gated+normed  [B,T,E]
__device__ float g_decay[H_*T_];        // gamma_h ^ d

// ---------------- SGEMM: C = A(MxK) * W(NxK)^T + bias ----------------
// M=4096, N=1024, K=1024. 128x128 tile, BK=8, 256 threads, 8x8 per thread.
// mode 0: scatter to [B,H,T,HD]; mode 1: silu -> [B,T,E]; mode 2: plain -> [B,T,E]
__global__ __launch_bounds__(256) void sgemm_kernel(
    const float* __restrict__ A, const float* __restrict__ W,
    const float* __restrict__ bias, float* __restrict__ C, int mode)
{
    __shared__ float As[8][128];
    __shared__ float Bs[8][128];
    const int bm = blockIdx.y * 128;
    const int bn = blockIdx.x * 128;
    const int tid = threadIdx.x;
    const int tx = tid & 15, ty = tid >> 4;

    float acc[8][8];
    #pragma unroll
    for (int i = 0; i < 8; i++)
        #pragma unroll
        for (int j = 0; j < 8; j++) acc[i][j] = 0.f;

    const int lr = tid >> 1;           // 0..127
    const int lc = (tid & 1) * 4;      // 0 or 4
    const float* Aptr = A + (size_t)(bm + lr) * 1024 + lc;
    const float* Wptr = W + (size_t)(bn + lr) * 1024 + lc;

    for (int k0 = 0; k0 < 1024; k0 += 8) {
        float4 a4 = *(const float4*)(Aptr + k0);
        float4 b4 = *(const float4*)(Wptr + k0);
        As[lc+0][lr] = a4.x; As[lc+1][lr] = a4.y; As[lc+2][lr] = a4.z; As[lc+3][lr] = a4.w;
        Bs[lc+0][lr] = b4.x; Bs[lc+1][lr] = b4.y; Bs[lc+2][lr] = b4.z; Bs[lc+3][lr] = b4.w;
        __syncthreads();
        #pragma unroll
        for (int kk = 0; kk < 8; kk++) {
            float ar[8], br[8];
            *(float4*)&ar[0] = *(const float4*)&As[kk][ty*8];
            *(float4*)&ar[4] = *(const float4*)&As[kk][ty*8 + 4];
            *(float4*)&br[0] = *(const float4*)&Bs[kk][tx*8];
            *(float4*)&br[4] = *(const float4*)&Bs[kk][tx*8 + 4];
            #pragma unroll
            for (int i = 0; i < 8; i++)
                #pragma unroll
                for (int j = 0; j < 8; j++)
                    acc[i][j] = fmaf(ar[i], br[j], acc[i][j]);
        }
        __syncthreads();
    }

    #pragma unroll
    for (int i = 0; i < 8; i++) {
        const int m = bm + ty*8 + i;
        const int b = m >> 11;           // m / 2048
        const int t = m & 2047;
        #pragma unroll
        for (int j = 0; j < 8; j++) {
            const int n = bn + tx*8 + j;
            float v = acc[i][j] + bias[n];
            if (mode == 0) {
                const int h  = n >> 6;
                const int hd = n & 63;
                C[(((size_t)(b*H_ + h) * T_ + t) * HD_) + hd] = v;
            } else if (mode == 1) {
                C[(size_t)m * E_ + n] = v / (1.f + __expf(-v)) ;
            } else {
                C[(size_t)m * E_ + n] = v;
            }
        }
    }
}

// ---------------- RoPE (in place on [B,H,T,HD]) ----------------
__global__ __launch_bounds__(256) void rope_kernel(float* __restrict__ X)
{
    __shared__ float invf[32];
    if (threadIdx.x < 32)
        invf[threadIdx.x] = (float)pow(10000.0, -(double)threadIdx.x / 32.0);
    __syncthreads();

    const int idx = blockIdx.x * 256 + threadIdx.x;   // pair index
    const int NPAIR = B_*H_*T_*(HD_/2);
    if (idx >= NPAIR) return;
    const int p   = idx & 31;          // pair within head dim
    const int row = idx >> 5;          // (b*H+h)*T + t
    const int t   = row & (T_ - 1);

    float* xp = X + (size_t)row * HD_ + p*2;
    const float x0 = xp[0], x1 = xp[1];
    const int i0 = (2*p)     & 31;
    const int i1 = (2*p + 1) & 31;
    float s0, c0, s1, c1;
    sincosf((float)t * invf[i0], &s0, &c0);
    sincosf((float)t * invf[i1], &s1, &c1);
    xp[0] = x0 * c0 - x1 * s0;
    xp[1] = x1 * c1 + x0 * s1;
}

// ---------------- decay table gamma_h^d (double precision) ----------------
__global__ void decay_kernel()
{
    const int idx = blockIdx.x * 256 + threadIdx.x;
    if (idx >= H_*T_) return;
    const int h = idx >> 11, d = idx & 2047;
    const double gamma = 1.0 - exp2(-(double)(5 + h));
    g_decay[idx] = (float)pow(gamma, (double)d);
}

// ---------------- attention: O = ((Q K^T)/8 * decay_mask) V ----------------
// Reference mask is UPPER-triangular: scores[i,j] kept when j >= i, decay gamma^(j-i).
// grid = (32 qtiles, 32 bh), 256 threads, 64x64 tiles.
__global__ __launch_bounds__(256) void attn_kernel()
{
    __shared__ float Qs[64][64];   // [r][k]
    __shared__ float KS[64][64];   // K^T [k][c], reused as S [r][c]
    __shared__ float Vs[64][64];   // [k][c]

    const int bh = blockIdx.y;
    const int b  = bh >> 4, h = bh & 15;
    const int qt = blockIdx.x;     // qt=0 is heaviest (attends all future tiles)
    const int q0 = qt * 64;

    const float* Qg = g_Q + (size_t)bh * T_ * HD_;
    const float* Kg = g_K + (size_t)bh * T_ * HD_;
    const float* Vg = g_V + (size_t)bh * T_ * HD_;
    const float* dec = g_decay + h * T_;

    const int tid = threadIdx.x;
    const int tx = tid & 15, ty = tid >> 4;
    const int lrow = tid >> 2, lseg = (tid & 3) * 16;

    // load Q tile (row major, coalesced)
    {
        const float4* src = (const float4*)(Qg + (size_t)(q0 + lrow) * 64 + lseg);
        float4* dst = (float4*)(&Qs[lrow][lseg]);
        dst[0] = src[0]; dst[1] = src[1]; dst[2] = src[2]; dst[3] = src[3];
    }

    float o[4][4];
    #pragma unroll
    for (int i = 0; i < 4; i++)
        #pragma unroll
        for (int j = 0; j < 4; j++) o[i][j] = 0.f;

    const float invsc = 0.125f;

    for (int jt = qt; jt < NT_; jt++) {
        const int j0 = jt * 64;
        __syncthreads();   // previous iter done reading KS/Vs (and 1st iter: no-op)
        {
            // K transposed into KS[k][c]
            float4 k4[4];
            const float4* ks = (const float4*)(Kg + (size_t)(j0 + lrow) * 64 + lseg);
            #pragma unroll
            for (int q = 0; q < 4; q++) k4[q] = ks[q];
            #pragma unroll
            for (int q = 0; q < 4; q++) {
                KS[lseg + q*4 + 0][lrow] = k4[q].x;
                KS[lseg + q*4 + 1][lrow] = k4[q].y;
                KS[lseg + q*4 + 2][lrow] = k4[q].z;
                KS[lseg + q*4 + 3][lrow] = k4[q].w;
            }
            // V straight copy
            const float4* vs = (const float4*)(Vg + (size_t)(j0 + lrow) * 64 + lseg);
            float4* vd = (float4*)(&Vs[lrow][lseg]);
            #pragma unroll
            for (int q = 0; q < 4; q++) vd[q] = vs[q];
        }
        __syncthreads();

        // S = Q K^T
        float s[4][4];
        #pragma unroll
        for (int i = 0; i < 4; i++)
            #pragma unroll
            for (int j = 0; j < 4; j++) s[i][j] = 0.f;

        #pragma unroll 8
        for (int k = 0; k < 64; k++) {
            float4 kv = *(const float4*)(&KS[k][tx*4]);
            float qv[4];
            #pragma unroll
            for (int i = 0; i < 4; i++) qv[i] = Qs[ty*4 + i][k];
            #pragma unroll
            for (int i = 0; i < 4; i++) {
                s[i][0] = fmaf(qv[i], kv.x, s[i][0]);
                s[i][1] = fmaf(qv[i], kv.y, s[i][1]);
                s[i][2] = fmaf(qv[i], kv.z, s[i][2]);
                s[i][3] = fmaf(qv[i], kv.w, s[i][3]);
            }
        }

        // scale + UPPER-triangular decay mask: keep j >= i with gamma^(j-i)
        #pragma unroll
        for (int i = 0; i < 4; i++) {
            const int m = q0 + ty*4 + i;
            #pragma unroll
            for (int j = 0; j < 4; j++) {
                const int n = j0 + tx*4 + j;
                s[i][j] = (n >= m) ? s[i][j] * invsc * dec[n - m] : 0.f;
            }
        }

        __syncthreads();   // everyone done reading KS as K
        #pragma unroll
        for (int i = 0; i < 4; i++)
            *(float4*)(&KS[ty*4 + i][tx*4]) = make_float4(s[i][0], s[i][1], s[i][2], s[i][3]);
        __syncthreads();

        // O += S V
        #pragma unroll 8
        for (int k = 0; k < 64; k++) {
            float4 vv = *(const float4*)(&Vs[k][tx*4]);
            float sv[4];
            #pragma unroll
            for (int i = 0; i < 4; i++) sv[i] = KS[ty*4 + i][k];
            #pragma unroll
            for (int i = 0; i < 4; i++) {
                o[i][0] = fmaf(sv[i], vv.x, o[i][0]);
                o[i][1] = fmaf(sv[i], vv.y, o[i][1]);
                o[i][2] = fmaf(sv[i], vv.z, o[i][2]);
                o[i][3] = fmaf(sv[i], vv.w, o[i][3]);
            }
        }
    }

    // write to [B,T,E]
    #pragma unroll
    for (int i = 0; i < 4; i++) {
        const int t = q0 + ty*4 + i;
        float* dst = g_O + ((size_t)(b*T_ + t)) * E_ + h*64 + tx*4;
        *(float4*)dst = make_float4(o[i][0], o[i][1], o[i][2], o[i][3]);
    }
}

// ---------------- GroupNorm over (HD,T) per (b,h), fused with gate multiply ----------------
__global__ __launch_bounds__(256) void gn_kernel(
    const float* __restrict__ gn_w, const float* __restrict__ gn_b)
{
    const int bh = blockIdx.x;
    const int b = bh >> 4, h = bh & 15;
    const size_t base = (size_t)b * T_ * E_ + h * 64;

    double sum = 0.0, sumsq = 0.0;
    for (int i = threadIdx.x; i < T_*64; i += 256) {
        const int t = i >> 6, hd = i & 63;
        const float v = g_O[base + (size_t)t * E_ + hd];
        sum += v;
        sumsq += (double)v * (double)v;
    }

    __shared__ double ssum[256], ssq[256];
    ssum[threadIdx.x] = sum; ssq[threadIdx.x] = sumsq;
    __syncthreads();
    for (int off = 128; off > 0; off >>= 1) {
        if (threadIdx.x < off) {
            ssum[threadIdx.x] += ssum[threadIdx.x + off];
            ssq[threadIdx.x]  += ssq[threadIdx.x + off];
        }
        __syncthreads();
    }
    const double N = (double)(T_*64);
    const double mu = ssum[0] / N;
    const double var = ssq[0] / N - mu * mu;
    const float muf = (float)mu;
    const float rs  = (float)(1.0 / sqrt(var + 1e-5));

    for (int i = threadIdx.x; i < T_*64; i += 256) {
        const int t = i >> 6, hd = i & 63;
        const int e = h*64 + hd;
        const size_t idx = (size_t)(b*T_ + t) * E_ + e;
        const float v = (g_O[idx] - muf) * rs * gn_w[e] + gn_b[e];
        g_GN[idx] = v * g_G[idx];
    }
}

// ---------------- launch ----------------
extern "C" void kernel_launch(void* const* d_in, const int* in_sizes, int n_in,
                              void* d_out, int out_size)
{
    const float* x    = (const float*)d_in[0];
    const float* Wq   = (const float*)d_in[1];
    const float* bq   = (const float*)d_in[2];
    const float* Wk   = (const float*)d_in[3];
    const float* bk   = (const float*)d_in[4];
    const float* Wv   = (const float*)d_in[5];
    const float* bv   = (const float*)d_in[6];
    const float* Wg   = (const float*)d_in[7];
    const float* bg   = (const float*)d_in[8];
    const float* Wo   = (const float*)d_in[9];
    const float* bo   = (const float*)d_in[10];
    const float* gn_w = (const float*)d_in[11];
    const float* gn_b = (const float*)d_in[12];

    float *Q, *K, *V, *G, *GN;
    cudaGetSymbolAddress((void**)&Q,  g_Q);
    cudaGetSymbolAddress((void**)&K,  g_K);
    cudaGetSymbolAddress((void**)&V,  g_V);
    cudaGetSymbolAddress((void**)&G,  g_G);
    cudaGetSymbolAddress((void**)&GN, g_GN);

    const dim3 gg(E_/128, M_/128);   // (8, 32)

    sgemm_kernel<<<gg, 256>>>(x, Wq, bq, Q, 0);
    sgemm_kernel<<<gg, 256>>>(x, Wk, bk, K, 0);
    sgemm_kernel<<<gg, 256>>>(x, Wv, bv, V, 0);
    sgemm_kernel<<<gg, 256>>>(x, Wg, bg, G, 1);

    const int npair = B_*H_*T_*(HD_/2);
    rope_kernel<<<(npair + 255)/256, 256>>>(Q);
    rope_kernel<<<(npair + 255)/256, 256>>>(K);

    decay_kernel<<<(H_*T_ + 255)/256, 256>>>();

    attn_kernel<<<dim3(NT_, B_*H_), 256>>>();

    gn_kernel<<<B_*H_, 256>>>(gn_w, gn_b);

    sgemm_kernel<<<gg, 256>>>(GN, Wo, bo, (float*)d_out, 2);
}

// round 3
// speedup vs baseline: 1.4445x; 1.4445x over previous
#include <cuda_runtime.h>
#include <math.h>

#define B_  2
#define T_  2048
#define E_  1024
#define H_  16
#define HD_ 64
#define M_  (B_*T_)   // 4096
#define NT_ (T_/64)   // 32 chunks of 64

// ---------------- scratch (static device globals; no allocation) ----------------
__device__ float g_Q[B_*H_*T_*HD_];     // [B,H,T,HD]
__device__ float g_K[B_*H_*T_*HD_];
__device__ float g_V[B_*H_*T_*HD_];
__device__ float g_G[B_*T_*E_];         // silu(gate)  [B,T,E]
__device__ float g_O[B_*T_*E_];         // attention out [B,T,E]
__device__ float g_GN[B_*T_*E_];        // gated+normed  [B,T,E]
__device__ float g_decay[H_*T_];        // gamma_h ^ d
__device__ float g_R[B_*H_*NT_*HD_*HD_]; // per-chunk states [bh][c][d][e], 16MB

// ---------------- SGEMM: C = A(MxK) * W(NxK)^T + bias ----------------
// 128x128 tile, BK=8 double-buffered, 256 threads, 8x8 per thread.
// single_mode < 0: z selects (W,b,C): z=0,1,2 scatter->[B,H,T,HD]; z=3 silu->[B,T,E]
// single_mode >= 0: use W0/b0/C0 with that mode (2 = plain flat)
__global__ __launch_bounds__(256, 2) void sgemm_kernel(
    const float* __restrict__ A,
    const float* __restrict__ W0, const float* __restrict__ b0,
    const float* __restrict__ W1, const float* __restrict__ b1,
    const float* __restrict__ W2, const float* __restrict__ b2,
    const float* __restrict__ W3, const float* __restrict__ b3,
    float* __restrict__ C0, float* __restrict__ C1,
    float* __restrict__ C2, float* __restrict__ C3,
    int single_mode)
{
    const float* W; const float* bias; float* C; int mode;
    if (single_mode >= 0) {
        W = W0; bias = b0; C = C0; mode = single_mode;
    } else {
        const int z = blockIdx.z;
        if      (z == 0) { W = W0; bias = b0; C = C0; mode = 0; }
        else if (z == 1) { W = W1; bias = b1; C = C1; mode = 0; }
        else if (z == 2) { W = W2; bias = b2; C = C2; mode = 0; }
        else             { W = W3; bias = b3; C = C3; mode = 1; }
    }

    __shared__ float As[2][8][128];
    __shared__ float Bs[2][8][128];
    const int bm = blockIdx.y * 128;
    const int bn = blockIdx.x * 128;
    const int tid = threadIdx.x;
    const int tx = tid & 15, ty = tid >> 4;

    float acc[8][8];
    #pragma unroll
    for (int i = 0; i < 8; i++)
        #pragma unroll
        for (int j = 0; j < 8; j++) acc[i][j] = 0.f;

    const int lr = tid >> 1;           // 0..127
    const int lc = (tid & 1) * 4;      // 0 or 4
    const float* Aptr = A + (size_t)(bm + lr) * 1024 + lc;
    const float* Wptr = W + (size_t)(bn + lr) * 1024 + lc;

    // prime buffer 0
    {
        float4 a4 = *(const float4*)(Aptr);
        float4 b4 = *(const float4*)(Wptr);
        As[0][lc+0][lr] = a4.x; As[0][lc+1][lr] = a4.y; As[0][lc+2][lr] = a4.z; As[0][lc+3][lr] = a4.w;
        Bs[0][lc+0][lr] = b4.x; Bs[0][lc+1][lr] = b4.y; Bs[0][lc+2][lr] = b4.z; Bs[0][lc+3][lr] = b4.w;
    }
    __syncthreads();

    int buf = 0;
    for (int k0 = 0; k0 < 1024; k0 += 8) {
        const bool more = (k0 + 8) < 1024;
        float4 a4n, b4n;
        if (more) {
            a4n = *(const float4*)(Aptr + k0 + 8);
            b4n = *(const float4*)(Wptr + k0 + 8);
        }
        #pragma unroll
        for (int kk = 0; kk < 8; kk++) {
            float ar[8], br[8];
            *(float4*)&ar[0] = *(const float4*)&As[buf][kk][ty*8];
            *(float4*)&ar[4] = *(const float4*)&As[buf][kk][ty*8 + 4];
            *(float4*)&br[0] = *(const float4*)&Bs[buf][kk][tx*8];
            *(float4*)&br[4] = *(const float4*)&Bs[buf][kk][tx*8 + 4];
            #pragma unroll
            for (int i = 0; i < 8; i++)
                #pragma unroll
                for (int j = 0; j < 8; j++)
                    acc[i][j] = fmaf(ar[i], br[j], acc[i][j]);
        }
        if (more) {
            const int nb = buf ^ 1;
            As[nb][lc+0][lr] = a4n.x; As[nb][lc+1][lr] = a4n.y; As[nb][lc+2][lr] = a4n.z; As[nb][lc+3][lr] = a4n.w;
            Bs[nb][lc+0][lr] = b4n.x; Bs[nb][lc+1][lr] = b4n.y; Bs[nb][lc+2][lr] = b4n.z; Bs[nb][lc+3][lr] = b4n.w;
            __syncthreads();
            buf = nb;
        }
    }

    #pragma unroll
    for (int i = 0; i < 8; i++) {
        const int m = bm + ty*8 + i;
        const int b = m >> 11;           // m / 2048
        const int t = m & 2047;
        #pragma unroll
        for (int j = 0; j < 8; j++) {
            const int n = bn + tx*8 + j;
            float v = acc[i][j] + bias[n];
            if (mode == 0) {
                const int h  = n >> 6;
                const int hd = n & 63;
                C[(((size_t)(b*H_ + h) * T_ + t) * HD_) + hd] = v;
            } else if (mode == 1) {
                C[(size_t)m * E_ + n] = v / (1.f + __expf(-v));
            } else {
                C[(size_t)m * E_ + n] = v;
            }
        }
    }
}

// ---------------- RoPE (in place on [B,H,T,HD]) ----------------
__global__ __launch_bounds__(256) void rope_kernel(float* __restrict__ X)
{
    __shared__ float invf[32];
    if (threadIdx.x < 32)
        invf[threadIdx.x] = (float)pow(10000.0, -(double)threadIdx.x / 32.0);
    __syncthreads();

    const int idx = blockIdx.x * 256 + threadIdx.x;   // pair index
    const int NPAIR = B_*H_*T_*(HD_/2);
    if (idx >= NPAIR) return;
    const int p   = idx & 31;          // pair within head dim
    const int row = idx >> 5;          // (b*H+h)*T + t
    const int t   = row & (T_ - 1);

    float* xp = X + (size_t)row * HD_ + p*2;
    const float x0 = xp[0], x1 = xp[1];
    const int i0 = (2*p)     & 31;
    const int i1 = (2*p + 1) & 31;
    float s0, c0, s1, c1;
    sincosf((float)t * invf[i0], &s0, &c0);
    sincosf((float)t * invf[i1], &s1, &c1);
    xp[0] = x0 * c0 - x1 * s0;
    xp[1] = x1 * c1 + x0 * s1;
}

// ---------------- decay table gamma_h^d (double precision) ----------------
__global__ void decay_kernel()
{
    const int idx = blockIdx.x * 256 + threadIdx.x;
    if (idx >= H_*T_) return;
    const int h = idx >> 11, d = idx & 2047;
    const double gamma = 1.0 - exp2(-(double)(5 + h));
    g_decay[idx] = (float)pow(gamma, (double)d);
}

// ---------------- Pass 1: backward chunk-state scan ----------------
// Reference mask keeps j >= i with gamma^(j-i)  (reversed-time retention).
// R_c[d][e] = sum_{j >= (c+1)*64} gamma^(j-(c+1)*64) K[j][d] V[j][e]
// Recurrence (backward): R_{cc-1} = (sum_i gamma^i k_{ccL+i} v^T) + gamma^64 * R_cc,  R_{31} = 0.
// grid = (4 e-blocks, 32 bh), 256 threads. Each block owns 16 V-columns of the state.
__global__ __launch_bounds__(256) void ret_state_kernel()
{
    __shared__ float Ks[64][64];
    __shared__ float Vs[64][16];
    __shared__ float dec_s[65];

    const int eb = blockIdx.x;         // 0..3
    const int bh = blockIdx.y;         // 0..31
    const int h  = bh & 15;
    const int tid = threadIdx.x;
    const int d  = tid >> 2;           // 0..63 (state row)
    const int eq = (tid & 3) * 4;      // 0,4,8,12 (local e quad)
    const int e0 = eb * 16;

    if (tid < 65) dec_s[tid] = g_decay[h*T_ + tid];

    const float* Kg = g_K + (size_t)bh * T_ * HD_;
    const float* Vg = g_V + (size_t)bh * T_ * HD_;
    float* Rg = g_R + (size_t)bh * NT_ * (HD_*HD_);

    const int lrow = tid >> 2, lseg = (tid & 3) * 16;

    float R0 = 0.f, R1 = 0.f, R2 = 0.f, R3 = 0.f;

    // R for last chunk is zero
    *(float4*)&Rg[((NT_-1)*64 + d)*64 + e0 + eq] = make_float4(0.f, 0.f, 0.f, 0.f);

    __syncthreads();                    // dec_s ready
    const float gL = dec_s[64];

    for (int cc = NT_ - 1; cc >= 1; --cc) {
        const int j0 = cc * 64;
        // load K chunk (row major) and V column slice
        {
            const float4* ks = (const float4*)(Kg + (size_t)(j0 + lrow) * 64 + lseg);
            float4* kd = (float4*)(&Ks[lrow][lseg]);
            #pragma unroll
            for (int q = 0; q < 4; q++) kd[q] = ks[q];
            *(float4*)&Vs[lrow][(tid & 3) * 4] =
                *(const float4*)(Vg + (size_t)(j0 + lrow) * 64 + e0 + (tid & 3) * 4);
        }
        __syncthreads();

        float a0 = 0.f, a1 = 0.f, a2 = 0.f, a3 = 0.f;
        #pragma unroll 8
        for (int i = 0; i < 64; i++) {
            const float kw = Ks[i][d] * dec_s[i];
            const float4 v = *(const float4*)&Vs[i][eq];
            a0 = fmaf(kw, v.x, a0);
            a1 = fmaf(kw, v.y, a1);
            a2 = fmaf(kw, v.z, a2);
            a3 = fmaf(kw, v.w, a3);
        }
        R0 = a0 + gL * R0;
        R1 = a1 + gL * R1;
        R2 = a2 + gL * R2;
        R3 = a3 + gL * R3;
        *(float4*)&Rg[((cc-1)*64 + d)*64 + e0 + eq] = make_float4(R0, R1, R2, R3);
        __syncthreads();   // before smem reuse next iter
    }
}

// ---------------- Pass 2: per-chunk intra + cross ----------------
// O[i][e] = sum_{j>=i in chunk} gamma^(j-i)/8 (q_i.k_j) V[j][e]
//         + gamma^(64-ii)/8 * sum_d Q[i][d] R_c[d][e]
// grid = (32 chunks, 32 bh), 256 threads, 64x64 tiles.
__global__ __launch_bounds__(256) void ret_attn_kernel()
{
    __shared__ float Qs[64][64];   // [r][k]
    __shared__ float KS[64][64];   // K^T [k][c], reused as S [r][c]
    __shared__ float Vs[64][64];   // [k][c]

    const int bh = blockIdx.y;
    const int b  = bh >> 4, h = bh & 15;
    const int c  = blockIdx.x;
    const int q0 = c * 64;

    const float* Qg = g_Q + (size_t)bh * T_ * HD_;
    const float* Kg = g_K + (size_t)bh * T_ * HD_;
    const float* Vg = g_V + (size_t)bh * T_ * HD_;
    const float* dec = g_decay + h * T_;
    const float* Rg = g_R + ((size_t)bh * NT_ + c) * (HD_*HD_);

    const int tid = threadIdx.x;
    const int tx = tid & 15, ty = tid >> 4;
    const int lrow = tid >> 2, lseg = (tid & 3) * 16;

    // load Q, K^T, V tiles
    {
        const float4* qsrc = (const float4*)(Qg + (size_t)(q0 + lrow) * 64 + lseg);
        float4* qdst = (float4*)(&Qs[lrow][lseg]);
        #pragma unroll
        for (int q = 0; q < 4; q++) qdst[q] = qsrc[q];

        float4 k4[4];
        const float4* ks = (const float4*)(Kg + (size_t)(q0 + lrow) * 64 + lseg);
        #pragma unroll
        for (int q = 0; q < 4; q++) k4[q] = ks[q];
        #pragma unroll
        for (int q = 0; q < 4; q++) {
            KS[lseg + q*4 + 0][lrow] = k4[q].x;
            KS[lseg + q*4 + 1][lrow] = k4[q].y;
            KS[lseg + q*4 + 2][lrow] = k4[q].z;
            KS[lseg + q*4 + 3][lrow] = k4[q].w;
        }
        const float4* vs = (const float4*)(Vg + (size_t)(q0 + lrow) * 64 + lseg);
        float4* vd = (float4*)(&Vs[lrow][lseg]);
        #pragma unroll
        for (int q = 0; q < 4; q++) vd[q] = vs[q];
    }
    __syncthreads();

    const float invsc = 0.125f;

    // S = Q K^T (intra-chunk)
    float s[4][4];
    #pragma unroll
    for (int i = 0; i < 4; i++)
        #pragma unroll
        for (int j = 0; j < 4; j++) s[i][j] = 0.f;

    #pragma unroll 8
    for (int k = 0; k < 64; k++) {
        float4 kv = *(const float4*)(&KS[k][tx*4]);
        float qv[4];
        #pragma unroll
        for (int i = 0; i < 4; i++) qv[i] = Qs[ty*4 + i][k];
        #pragma unroll
        for (int i = 0; i < 4; i++) {
            s[i][0] = fmaf(qv[i], kv.x, s[i][0]);
            s[i][1] = fmaf(qv[i], kv.y, s[i][1]);
            s[i][2] = fmaf(qv[i], kv.z, s[i][2]);
            s[i][3] = fmaf(qv[i], kv.w, s[i][3]);
        }
    }

    // scale + local upper-triangular decay mask
    #pragma unroll
    for (int i = 0; i < 4; i++) {
        const int ii = ty*4 + i;
        #pragma unroll
        for (int j = 0; j < 4; j++) {
            const int jj = tx*4 + j;
            s[i][j] = (jj >= ii) ? s[i][j] * invsc * dec[jj - ii] : 0.f;
        }
    }

    __syncthreads();   // done reading KS as K
    #pragma unroll
    for (int i = 0; i < 4; i++)
        *(float4*)(&KS[ty*4 + i][tx*4]) = make_float4(s[i][0], s[i][1], s[i][2], s[i][3]);
    __syncthreads();

    // O = S V
    float o[4][4];
    #pragma unroll
    for (int i = 0; i < 4; i++)
        #pragma unroll
        for (int j = 0; j < 4; j++) o[i][j] = 0.f;

    #pragma unroll 8
    for (int k = 0; k < 64; k++) {
        float4 vv = *(const float4*)(&Vs[k][tx*4]);
        float sv[4];
        #pragma unroll
        for (int i = 0; i < 4; i++) sv[i] = KS[ty*4 + i][k];
        #pragma unroll
        for (int i = 0; i < 4; i++) {
            o[i][0] = fmaf(sv[i], vv.x, o[i][0]);
            o[i][1] = fmaf(sv[i], vv.y, o[i][1]);
            o[i][2] = fmaf(sv[i], vv.z, o[i][2]);
            o[i][3] = fmaf(sv[i], vv.w, o[i][3]);
        }
    }

    // cross-chunk: cr = Q @ R_c, then o += coef_i * cr
    float cr[4][4];
    #pragma unroll
    for (int i = 0; i < 4; i++)
        #pragma unroll
        for (int j = 0; j < 4; j++) cr[i][j] = 0.f;

    #pragma unroll 4
    for (int d = 0; d < 64; d++) {
        const float4 rv = __ldg((const float4*)&Rg[d*64 + tx*4]);
        float qd[4];
        #pragma unroll
        for (int i = 0; i < 4; i++) qd[i] = Qs[ty*4 + i][d];
        #pragma unroll
        for (int i = 0; i < 4; i++) {
            cr[i][0] = fmaf(qd[i], rv.x, cr[i][0]);
            cr[i][1] = fmaf(qd[i], rv.y, cr[i][1]);
            cr[i][2] = fmaf(qd[i], rv.z, cr[i][2]);
            cr[i][3] = fmaf(qd[i], rv.w, cr[i][3]);
        }
    }

    #pragma unroll
    for (int i = 0; i < 4; i++) {
        const int ii = ty*4 + i;
        const float coef = invsc * dec[64 - ii];
        #pragma unroll
        for (int j = 0; j < 4; j++) o[i][j] = fmaf(coef, cr[i][j], o[i][j]);
    }

    // write to [B,T,E]
    #pragma unroll
    for (int i = 0; i < 4; i++) {
        const int t = q0 + ty*4 + i;
        float* dst = g_O + ((size_t)(b*T_ + t)) * E_ + h*64 + tx*4;
        *(float4*)dst = make_float4(o[i][0], o[i][1], o[i][2], o[i][3]);
    }
}

// ---------------- GroupNorm over (HD,T) per (b,h), fused with gate multiply ----------------
__global__ __launch_bounds__(256) void gn_kernel(
    const float* __restrict__ gn_w, const float* __restrict__ gn_b)
{
    const int bh = blockIdx.x;
    const int b = bh >> 4, h = bh & 15;
    const size_t base = (size_t)b * T_ * E_ + h * 64;

    double sum = 0.0, sumsq = 0.0;
    for (int i = threadIdx.x; i < T_*64; i += 256) {
        const int t = i >> 6, hd = i & 63;
        const float v = g_O[base + (size_t)t * E_ + hd];
        sum += v;
        sumsq += (double)v * (double)v;
    }

    __shared__ double ssum[256], ssq[256];
    ssum[threadIdx.x] = sum; ssq[threadIdx.x] = sumsq;
    __syncthreads();
    for (int off = 128; off > 0; off >>= 1) {
        if (threadIdx.x < off) {
            ssum[threadIdx.x] += ssum[threadIdx.x + off];
            ssq[threadIdx.x]  += ssq[threadIdx.x + off];
        }
        __syncthreads();
    }
    const double N = (double)(T_*64);
    const double mu = ssum[0] / N;
    const double var = ssq[0] / N - mu * mu;
    const float muf = (float)mu;
    const float rs  = (float)(1.0 / sqrt(var + 1e-5));

    for (int i = threadIdx.x; i < T_*64; i += 256) {
        const int t = i >> 6, hd = i & 63;
        const int e = h*64 + hd;
        const size_t idx = (size_t)(b*T_ + t) * E_ + e;
        const float v = (g_O[idx] - muf) * rs * gn_w[e] + gn_b[e];
        g_GN[idx] = v * g_G[idx];
    }
}

// ---------------- launch ----------------
extern "C" void kernel_launch(void* const* d_in, const int* in_sizes, int n_in,
                              void* d_out, int out_size)
{
    const float* x    = (const float*)d_in[0];
    const float* Wq   = (const float*)d_in[1];
    const float* bq   = (const float*)d_in[2];
    const float* Wk   = (const float*)d_in[3];
    const float* bk   = (const float*)d_in[4];
    const float* Wv   = (const float*)d_in[5];
    const float* bv   = (const float*)d_in[6];
    const float* Wg   = (const float*)d_in[7];
    const float* bg   = (const float*)d_in[8];
    const float* Wo   = (const float*)d_in[9];
    const float* bo   = (const float*)d_in[10];
    const float* gn_w = (const float*)d_in[11];
    const float* gn_b = (const float*)d_in[12];

    float *Q, *K, *V, *G, *GN;
    cudaGetSymbolAddress((void**)&Q,  g_Q);
    cudaGetSymbolAddress((void**)&K,  g_K);
    cudaGetSymbolAddress((void**)&V,  g_V);
    cudaGetSymbolAddress((void**)&G,  g_G);
    cudaGetSymbolAddress((void**)&GN, g_GN);

    decay_kernel<<<(H_*T_ + 255)/256, 256>>>();

    // fused Q,K,V,G projections: one launch, grid.z selects weight
    sgemm_kernel<<<dim3(E_/128, M_/128, 4), 256>>>(
        x, Wq, bq, Wk, bk, Wv, bv, Wg, bg, Q, K, V, G, -1);

    const int npair = B_*H_*T_*(HD_/2);
    rope_kernel<<<(npair + 255)/256, 256>>>(Q);
    rope_kernel<<<(npair + 255)/256, 256>>>(K);

    ret_state_kernel<<<dim3(4, B_*H_), 256>>>();
    ret_attn_kernel<<<dim3(NT_, B_*H_), 256>>>();

    gn_kernel<<<B_*H_, 256>>>(gn_w, gn_b);

    sgemm_kernel<<<dim3(E_/128, M_/128, 1), 256>>>(
        GN, Wo, bo, nullptr, nullptr, nullptr, nullptr, nullptr, nullptr,
        (float*)d_out, nullptr, nullptr, nullptr, 2);
}

// round 4
// speedup vs baseline: 1.4449x; 1.0003x over previous
#include <cuda_runtime.h>
#include <math.h>

#define B_  2
#define T_  2048
#define E_  1024
#define H_  16
#define HD_ 64
#define M_  (B_*T_)   // 4096
#define NT_ (T_/64)   // 32 chunks of 64

// ---------------- scratch (static device globals; no allocation) ----------------
__device__ float g_Q[B_*H_*T_*HD_];     // [B,H,T,HD]
__device__ float g_K[B_*H_*T_*HD_];
__device__ float g_V[B_*H_*T_*HD_];
__device__ float g_G[B_*T_*E_];         // silu(gate)  [B,T,E]
__device__ float g_O[B_*T_*E_];         // attention out [B,T,E]
__device__ float g_GN[B_*T_*E_];        // gated+normed  [B,T,E]
__device__ float g_decay[H_*T_];        // gamma_h ^ d
__device__ float g_R[B_*H_*NT_*HD_*HD_]; // per-chunk states [bh][c][d][e], 16MB

// ---------------- SGEMM: C = A(MxK) * W(NxK)^T + bias ----------------
// 128x128 tile, BK=8 double-buffered, 256 threads, 8x8 per thread.
// single_mode < 0: z selects (W,b,C): z=0,1,2 scatter->[B,H,T,HD]; z=3 silu->[B,T,E]
// single_mode >= 0: use W0/b0/C0 with that mode (2 = plain flat)
__global__ __launch_bounds__(256, 2) void sgemm_kernel(
    const float* __restrict__ A,
    const float* __restrict__ W0, const float* __restrict__ b0,
    const float* __restrict__ W1, const float* __restrict__ b1,
    const float* __restrict__ W2, const float* __restrict__ b2,
    const float* __restrict__ W3, const float* __restrict__ b3,
    float* __restrict__ C0, float* __restrict__ C1,
    float* __restrict__ C2, float* __restrict__ C3,
    int single_mode)
{
    const float* W; const float* bias; float* C; int mode;
    if (single_mode >= 0) {
        W = W0; bias = b0; C = C0; mode = single_mode;
    } else {
        const int z = blockIdx.z;
        if      (z == 0) { W = W0; bias = b0; C = C0; mode = 0; }
        else if (z == 1) { W = W1; bias = b1; C = C1; mode = 0; }
        else if (z == 2) { W = W2; bias = b2; C = C2; mode = 0; }
        else             { W = W3; bias = b3; C = C3; mode = 1; }
    }

    __shared__ float As[2][8][128];
    __shared__ float Bs[2][8][128];
    const int bm = blockIdx.y * 128;
    const int bn = blockIdx.x * 128;
    const int tid = threadIdx.x;
    const int tx = tid & 15, ty = tid >> 4;

    float acc[8][8];
    #pragma unroll
    for (int i = 0; i < 8; i++)
        #pragma unroll
        for (int j = 0; j < 8; j++) acc[i][j] = 0.f;

    const int lr = tid >> 1;           // 0..127
    const int lc = (tid & 1) * 4;      // 0 or 4
    const float* Aptr = A + (size_t)(bm + lr) * 1024 + lc;
    const float* Wptr = W + (size_t)(bn + lr) * 1024 + lc;

    // prime buffer 0
    {
        float4 a4 = *(const float4*)(Aptr);
        float4 b4 = *(const float4*)(Wptr);
        As[0][lc+0][lr] = a4.x; As[0][lc+1][lr] = a4.y; As[0][lc+2][lr] = a4.z; As[0][lc+3][lr] = a4.w;
        Bs[0][lc+0][lr] = b4.x; Bs[0][lc+1][lr] = b4.y; Bs[0][lc+2][lr] = b4.z; Bs[0][lc+3][lr] = b4.w;
    }
    __syncthreads();

    int buf = 0;
    for (int k0 = 0; k0 < 1024; k0 += 8) {
        const bool more = (k0 + 8) < 1024;
        float4 a4n, b4n;
        if (more) {
            a4n = *(const float4*)(Aptr + k0 + 8);
            b4n = *(const float4*)(Wptr + k0 + 8);
        }
        #pragma unroll
        for (int kk = 0; kk < 8; kk++) {
            float ar[8], br[8];
            *(float4*)&ar[0] = *(const float4*)&As[buf][kk][ty*8];
            *(float4*)&ar[4] = *(const float4*)&As[buf][kk][ty*8 + 4];
            *(float4*)&br[0] = *(const float4*)&Bs[buf][kk][tx*8];
            *(float4*)&br[4] = *(const float4*)&Bs[buf][kk][tx*8 + 4];
            #pragma unroll
            for (int i = 0; i < 8; i++)
                #pragma unroll
                for (int j = 0; j < 8; j++)
                    acc[i][j] = fmaf(ar[i], br[j], acc[i][j]);
        }
        if (more) {
            const int nb = buf ^ 1;
            As[nb][lc+0][lr] = a4n.x; As[nb][lc+1][lr] = a4n.y; As[nb][lc+2][lr] = a4n.z; As[nb][lc+3][lr] = a4n.w;
            Bs[nb][lc+0][lr] = b4n.x; Bs[nb][lc+1][lr] = b4n.y; Bs[nb][lc+2][lr] = b4n.z; Bs[nb][lc+3][lr] = b4n.w;
            __syncthreads();
            buf = nb;
        }
    }

    #pragma unroll
    for (int i = 0; i < 8; i++) {
        const int m = bm + ty*8 + i;
        const int b = m >> 11;           // m / 2048
        const int t = m & 2047;
        #pragma unroll
        for (int j = 0; j < 8; j++) {
            const int n = bn + tx*8 + j;
            float v = acc[i][j] + bias[n];
            if (mode == 0) {
                const int h  = n >> 6;
                const int hd = n & 63;
                C[(((size_t)(b*H_ + h) * T_ + t) * HD_) + hd] = v;
            } else if (mode == 1) {
                C[(size_t)m * E_ + n] = v / (1.f + __expf(-v));
            } else {
                C[(size_t)m * E_ + n] = v;
            }
        }
    }
}

// ---------------- RoPE (in place on [B,H,T,HD]) ----------------
__global__ __launch_bounds__(256) void rope_kernel(float* __restrict__ X)
{
    __shared__ float invf[32];
    if (threadIdx.x < 32)
        invf[threadIdx.x] = (float)pow(10000.0, -(double)threadIdx.x / 32.0);
    __syncthreads();

    const int idx = blockIdx.x * 256 + threadIdx.x;   // pair index
    const int NPAIR = B_*H_*T_*(HD_/2);
    if (idx >= NPAIR) return;
    const int p   = idx & 31;          // pair within head dim
    const int row = idx >> 5;          // (b*H+h)*T + t
    const int t   = row & (T_ - 1);

    float* xp = X + (size_t)row * HD_ + p*2;
    const float x0 = xp[0], x1 = xp[1];
    const int i0 = (2*p)     & 31;
    const int i1 = (2*p + 1) & 31;
    float s0, c0, s1, c1;
    sincosf((float)t * invf[i0], &s0, &c0);
    sincosf((float)t * invf[i1], &s1, &c1);
    xp[0] = x0 * c0 - x1 * s0;
    xp[1] = x1 * c1 + x0 * s1;
}

// ---------------- decay table gamma_h^d (double precision) ----------------
__global__ void decay_kernel()
{
    const int idx = blockIdx.x * 256 + threadIdx.x;
    if (idx >= H_*T_) return;
    const int h = idx >> 11, d = idx & 2047;
    const double gamma = 1.0 - exp2(-(double)(5 + h));
    g_decay[idx] = (float)pow(gamma, (double)d);
}

// ---------------- Pass 1: backward chunk-state scan ----------------
// Reference mask keeps j >= i with gamma^(j-i)  (reversed-time retention).
// R_c[d][e] = sum_{j >= (c+1)*64} gamma^(j-(c+1)*64) K[j][d] V[j][e]
// Recurrence (backward): R_{cc-1} = (sum_i gamma^i k_{ccL+i} v^T) + gamma^64 * R_cc,  R_{31} = 0.
// grid = (4 e-blocks, 32 bh), 256 threads. Each block owns 16 V-columns of the state.
__global__ __launch_bounds__(256) void ret_state_kernel()
{
    __shared__ float Ks[64][64];
    __shared__ float Vs[64][16];
    __shared__ float dec_s[65];

    const int eb = blockIdx.x;         // 0..3
    const int bh = blockIdx.y;         // 0..31
    const int h  = bh & 15;
    const int tid = threadIdx.x;
    const int d  = tid >> 2;           // 0..63 (state row)
    const int eq = (tid & 3) * 4;      // 0,4,8,12 (local e quad)
    const int e0 = eb * 16;

    if (tid < 65) dec_s[tid] = g_decay[h*T_ + tid];

    const float* Kg = g_K + (size_t)bh * T_ * HD_;
    const float* Vg = g_V + (size_t)bh * T_ * HD_;
    float* Rg = g_R + (size_t)bh * NT_ * (HD_*HD_);

    const int lrow = tid >> 2, lseg = (tid & 3) * 16;

    float R0 = 0.f, R1 = 0.f, R2 = 0.f, R3 = 0.f;

    // R for last chunk is zero
    *(float4*)&Rg[((NT_-1)*64 + d)*64 + e0 + eq] = make_float4(0.f, 0.f, 0.f, 0.f);

    __syncthreads();                    // dec_s ready
    const float gL = dec_s[64];

    for (int cc = NT_ - 1; cc >= 1; --cc) {
        const int j0 = cc * 64;
        // load K chunk (row major) and V column slice
        {
            const float4* ks = (const float4*)(Kg + (size_t)(j0 + lrow) * 64 + lseg);
            float4* kd = (float4*)(&Ks[lrow][lseg]);
            #pragma unroll
            for (int q = 0; q < 4; q++) kd[q] = ks[q];
            *(float4*)&Vs[lrow][(tid & 3) * 4] =
                *(const float4*)(Vg + (size_t)(j0 + lrow) * 64 + e0 + (tid & 3) * 4);
        }
        __syncthreads();

        float a0 = 0.f, a1 = 0.f, a2 = 0.f, a3 = 0.f;
        #pragma unroll 8
        for (int i = 0; i < 64; i++) {
            const float kw = Ks[i][d] * dec_s[i];
            const float4 v = *(const float4*)&Vs[i][eq];
            a0 = fmaf(kw, v.x, a0);
            a1 = fmaf(kw, v.y, a1);
            a2 = fmaf(kw, v.z, a2);
            a3 = fmaf(kw, v.w, a3);
        }
        R0 = a0 + gL * R0;
        R1 = a1 + gL * R1;
        R2 = a2 + gL * R2;
        R3 = a3 + gL * R3;
        *(float4*)&Rg[((cc-1)*64 + d)*64 + e0 + eq] = make_float4(R0, R1, R2, R3);
        __syncthreads();   // before smem reuse next iter
    }
}

// ---------------- Pass 2: per-chunk intra + cross ----------------
// O[i][e] = sum_{j>=i in chunk} gamma^(j-i)/8 (q_i.k_j) V[j][e]
//         + gamma^(64-ii)/8 * sum_d Q[i][d] R_c[d][e]
// grid = (32 chunks, 32 bh), 256 threads, 64x64 tiles.
__global__ __launch_bounds__(256) void ret_attn_kernel()
{
    __shared__ float Qs[64][64];   // [r][k]
    __shared__ float KS[64][64];   // K^T [k][c], reused as S [r][c]
    __shared__ float Vs[64][64];   // [k][c]

    const int bh = blockIdx.y;
    const int b  = bh >> 4, h = bh & 15;
    const int c  = blockIdx.x;
    const int q0 = c * 64;

    const float* Qg = g_Q + (size_t)bh * T_ * HD_;
    const float* Kg = g_K + (size_t)bh * T_ * HD_;
    const float* Vg = g_V + (size_t)bh * T_ * HD_;
    const float* dec = g_decay + h * T_;
    const float* Rg = g_R + ((size_t)bh * NT_ + c) * (HD_*HD_);

    const int tid = threadIdx.x;
    const int tx = tid & 15, ty = tid >> 4;
    const int lrow = tid >> 2, lseg = (tid & 3) * 16;

    // load Q, K^T, V tiles
    {
        const float4* qsrc = (const float4*)(Qg + (size_t)(q0 + lrow) * 64 + lseg);
        float4* qdst = (float4*)(&Qs[lrow][lseg]);
        #pragma unroll
        for (int q = 0; q < 4; q++) qdst[q] = qsrc[q];

        float4 k4[4];
        const float4* ks = (const float4*)(Kg + (size_t)(q0 + lrow) * 64 + lseg);
        #pragma unroll
        for (int q = 0; q < 4; q++) k4[q] = ks[q];
        #pragma unroll
        for (int q = 0; q < 4; q++) {
            KS[lseg + q*4 + 0][lrow] = k4[q].x;
            KS[lseg + q*4 + 1][lrow] = k4[q].y;
            KS[lseg + q*4 + 2][lrow] = k4[q].z;
            KS[lseg + q*4 + 3][lrow] = k4[q].w;
        }
        const float4* vs = (const float4*)(Vg + (size_t)(q0 + lrow) * 64 + lseg);
        float4* vd = (float4*)(&Vs[lrow][lseg]);
        #pragma unroll
        for (int q = 0; q < 4; q++) vd[q] = vs[q];
    }
    __syncthreads();

    const float invsc = 0.125f;

    // S = Q K^T (intra-chunk)
    float s[4][4];
    #pragma unroll
    for (int i = 0; i < 4; i++)
        #pragma unroll
        for (int j = 0; j < 4; j++) s[i][j] = 0.f;

    #pragma unroll 8
    for (int k = 0; k < 64; k++) {
        float4 kv = *(const float4*)(&KS[k][tx*4]);
        float qv[4];
        #pragma unroll
        for (int i = 0; i < 4; i++) qv[i] = Qs[ty*4 + i][k];
        #pragma unroll
        for (int i = 0; i < 4; i++) {
            s[i][0] = fmaf(qv[i], kv.x, s[i][0]);
            s[i][1] = fmaf(qv[i], kv.y, s[i][1]);
            s[i][2] = fmaf(qv[i], kv.z, s[i][2]);
            s[i][3] = fmaf(qv[i], kv.w, s[i][3]);
        }
    }

    // scale + local upper-triangular decay mask
    #pragma unroll
    for (int i = 0; i < 4; i++) {
        const int ii = ty*4 + i;
        #pragma unroll
        for (int j = 0; j < 4; j++) {
            const int jj = tx*4 + j;
            s[i][j] = (jj >= ii) ? s[i][j] * invsc * dec[jj - ii] : 0.f;
        }
    }

    __syncthreads();   // done reading KS as K
    #pragma unroll
    for (int i = 0; i < 4; i++)
        *(float4*)(&KS[ty*4 + i][tx*4]) = make_float4(s[i][0], s[i][1], s[i][2], s[i][3]);
    __syncthreads();

    // O = S V
    float o[4][4];
    #pragma unroll
    for (int i = 0; i < 4; i++)
        #pragma unroll
        for (int j = 0; j < 4; j++) o[i][j] = 0.f;

    #pragma unroll 8
    for (int k = 0; k < 64; k++) {
        float4 vv = *(const float4*)(&Vs[k][tx*4]);
        float sv[4];
        #pragma unroll
        for (int i = 0; i < 4; i++) sv[i] = KS[ty*4 + i][k];
        #pragma unroll
        for (int i = 0; i < 4; i++) {
            o[i][0] = fmaf(sv[i], vv.x, o[i][0]);
            o[i][1] = fmaf(sv[i], vv.y, o[i][1]);
            o[i][2] = fmaf(sv[i], vv.z, o[i][2]);
            o[i][3] = fmaf(sv[i], vv.w, o[i][3]);
        }
    }

    // cross-chunk: cr = Q @ R_c, then o += coef_i * cr
    float cr[4][4];
    #pragma unroll
    for (int i = 0; i < 4; i++)
        #pragma unroll
        for (int j = 0; j < 4; j++) cr[i][j] = 0.f;

    #pragma unroll 4
    for (int d = 0; d < 64; d++) {
        const float4 rv = __ldg((const float4*)&Rg[d*64 + tx*4]);
        float qd[4];
        #pragma unroll
        for (int i = 0; i < 4; i++) qd[i] = Qs[ty*4 + i][d];
        #pragma unroll
        for (int i = 0; i < 4; i++) {
            cr[i][0] = fmaf(qd[i], rv.x, cr[i][0]);
            cr[i][1] = fmaf(qd[i], rv.y, cr[i][1]);
            cr[i][2] = fmaf(qd[i], rv.z, cr[i][2]);
            cr[i][3] = fmaf(qd[i], rv.w, cr[i][3]);
        }
    }

    #pragma unroll
    for (int i = 0; i < 4; i++) {
        const int ii = ty*4 + i;
        const float coef = invsc * dec[64 - ii];
        #pragma unroll
        for (int j = 0; j < 4; j++) o[i][j] = fmaf(coef, cr[i][j], o[i][j]);
    }

    // write to [B,T,E]
    #pragma unroll
    for (int i = 0; i < 4; i++) {
        const int t = q0 + ty*4 + i;
        float* dst = g_O + ((size_t)(b*T_ + t)) * E_ + h*64 + tx*4;
        *(float4*)dst = make_float4(o[i][0], o[i][1], o[i][2], o[i][3]);
    }
}

// ---------------- GroupNorm over (HD,T) per (b,h), fused with gate multiply ----------------
__global__ __launch_bounds__(256) void gn_kernel(
    const float* __restrict__ gn_w, const float* __restrict__ gn_b)
{
    const int bh = blockIdx.x;
    const int b = bh >> 4, h = bh & 15;
    const size_t base = (size_t)b * T_ * E_ + h * 64;

    double sum = 0.0, sumsq = 0.0;
    for (int i = threadIdx.x; i < T_*64; i += 256) {
        const int t = i >> 6, hd = i & 63;
        const float v = g_O[base + (size_t)t * E_ + hd];
        sum += v;
        sumsq += (double)v * (double)v;
    }

    __shared__ double ssum[256], ssq[256];
    ssum[threadIdx.x] = sum; ssq[threadIdx.x] = sumsq;
    __syncthreads();
    for (int off = 128; off > 0; off >>= 1) {
        if (threadIdx.x < off) {
            ssum[threadIdx.x] += ssum[threadIdx.x + off];
            ssq[threadIdx.x]  += ssq[threadIdx.x + off];
        }
        __syncthreads();
    }
    const double N = (double)(T_*64);
    const double mu = ssum[0] / N;
    const double var = ssq[0] / N - mu * mu;
    const float muf = (float)mu;
    const float rs  = (float)(1.0 / sqrt(var + 1e-5));

    for (int i = threadIdx.x; i < T_*64; i += 256) {
        const int t = i >> 6, hd = i & 63;
        const int e = h*64 + hd;
        const size_t idx = (size_t)(b*T_ + t) * E_ + e;
        const float v = (g_O[idx] - muf) * rs * gn_w[e] + gn_b[e];
        g_GN[idx] = v * g_G[idx];
    }
}

// ---------------- launch ----------------
extern "C" void kernel_launch(void* const* d_in, const int* in_sizes, int n_in,
                              void* d_out, int out_size)
{
    const float* x    = (const float*)d_in[0];
    const float* Wq   = (const float*)d_in[1];
    const float* bq   = (const float*)d_in[2];
    const float* Wk   = (const float*)d_in[3];
    const float* bk   = (const float*)d_in[4];
    const float* Wv   = (const float*)d_in[5];
    const float* bv   = (const float*)d_in[6];
    const float* Wg   = (const float*)d_in[7];
    const float* bg   = (const float*)d_in[8];
    const float* Wo   = (const float*)d_in[9];
    const float* bo   = (const float*)d_in[10];
    const float* gn_w = (const float*)d_in[11];
    const float* gn_b = (const float*)d_in[12];

    float *Q, *K, *V, *G, *GN;
    cudaGetSymbolAddress((void**)&Q,  g_Q);
    cudaGetSymbolAddress((void**)&K,  g_K);
    cudaGetSymbolAddress((void**)&V,  g_V);
    cudaGetSymbolAddress((void**)&G,  g_G);
    cudaGetSymbolAddress((void**)&GN, g_GN);

    decay_kernel<<<(H_*T_ + 255)/256, 256>>>();

    // fused Q,K,V,G projections: one launch, grid.z selects weight
    sgemm_kernel<<<dim3(E_/128, M_/128, 4), 256>>>(
        x, Wq, bq, Wk, bk, Wv, bv, Wg, bg, Q, K, V, G, -1);

    const int npair = B_*H_*T_*(HD_/2);
    rope_kernel<<<(npair + 255)/256, 256>>>(Q);
    rope_kernel<<<(npair + 255)/256, 256>>>(K);

    ret_state_kernel<<<dim3(4, B_*H_), 256>>>();
    ret_attn_kernel<<<dim3(NT_, B_*H_), 256>>>();

    gn_kernel<<<B_*H_, 256>>>(gn_w, gn_b);

    sgemm_kernel<<<dim3(E_/128, M_/128, 1), 256>>>(
        GN, Wo, bo, nullptr, nullptr, nullptr, nullptr, nullptr, nullptr,
        (float*)d_out, nullptr, nullptr, nullptr, 2);
}

// round 6
// speedup vs baseline: 2.1314x; 1.4751x over previous
#include <cuda_runtime.h>
#include <cuda_bf16.h>
#include <math.h>
#include <stdint.h>

#define B_  2
#define T_  2048
#define E_  1024
#define H_  16
#define HD_ 64
#define M_  (B_*T_)
#define NT_ (T_/64)

#define TSTRIDE 80                   // bytes per smem tile row (32 bf16 + 8 pad)
#define TILE_BYTES (128*TSTRIDE)     // 10240
#define BUF_BYTES (4*TILE_BYTES)     // 40960
#define DYN_SMEM (2*BUF_BYTES)       // 81920

// ---------------- scratch ----------------
__device__ float g_Q[B_*H_*T_*HD_];
__device__ float g_K[B_*H_*T_*HD_];
__device__ float g_V[B_*H_*T_*HD_];
__device__ float g_G[B_*T_*E_];
__device__ float g_O[B_*T_*E_];
__device__ float g_decay[H_*T_];
__device__ float g_R[B_*H_*NT_*HD_*HD_];
__device__ float4 g_rope[T_*32];
__device__ __nv_bfloat16 g_Ah[M_*E_], g_Al[M_*E_];
__device__ __nv_bfloat16 g_Wh[5*E_*E_], g_Wl[5*E_*E_];

// ---------------- helpers ----------------
__device__ __forceinline__ uint32_t smem_u32(const void* p){
    uint32_t a; asm("{ .reg .u64 t; cvta.to.shared.u64 t, %1; cvt.u32.u64 %0, t; }":"=r"(a):"l"(p)); return a;
}
__device__ __forceinline__ void ldsm4(uint32_t r[4], uint32_t a){
    asm volatile("ldmatrix.sync.aligned.m8n8.x4.shared.b16 {%0,%1,%2,%3}, [%4];"
        :"=r"(r[0]),"=r"(r[1]),"=r"(r[2]),"=r"(r[3]):"r"(a));
}
__device__ __forceinline__ void mma16816(float c[4], const uint32_t a[4], const uint32_t b[2]){
    asm volatile("mma.sync.aligned.m16n8k16.row.col.f32.bf16.bf16.f32 "
        "{%0,%1,%2,%3}, {%4,%5,%6,%7}, {%8,%9}, {%0,%1,%2,%3};"
        : "+f"(c[0]),"+f"(c[1]),"+f"(c[2]),"+f"(c[3])
        : "r"(a[0]),"r"(a[1]),"r"(a[2]),"r"(a[3]),"r"(b[0]),"r"(b[1]));
}
#define CPA16(dst, src)  asm volatile("cp.async.cg.shared.global [%0], [%1], 16;"::"r"(dst),"l"(src))
#define CPA_COMMIT()     asm volatile("cp.async.commit_group;":::"memory")
#define CPA_WAIT(n)      asm volatile("cp.async.wait_group %0;"::"n"(n):"memory")

// ---------------- prep ----------------
__global__ void split_kernel(const float* __restrict__ src, __nv_bfloat16* __restrict__ hi,
                             __nv_bfloat16* __restrict__ lo, int n)
{
    int i = blockIdx.x*256 + threadIdx.x;
    if (i >= n) return;
    float v = src[i];
    __nv_bfloat16 h = __float2bfloat16(v);
    hi[i] = h; lo[i] = __float2bfloat16(v - __bfloat162float(h));
}

__global__ void decay_kernel()
{
    const int idx = blockIdx.x*256 + threadIdx.x;
    if (idx >= H_*T_) return;
    const int h = idx >> 11, d = idx & 2047;
    const double gamma = 1.0 - exp2(-(double)(5 + h));
    g_decay[idx] = (float)pow(gamma, (double)d);
}

__global__ void rope_table_kernel()
{
    int idx = blockIdx.x*256 + threadIdx.x;
    if (idx >= T_*32) return;
    int t = idx >> 5, p = idx & 31;
    float inv0 = (float)pow(10000.0, -(double)((2*p)   & 31) / 32.0);
    float inv1 = (float)pow(10000.0, -(double)((2*p+1) & 31) / 32.0);
    float s0,c0,s1,c1;
    sincosf((float)t * inv0, &s0, &c0);
    sincosf((float)t * inv1, &s1, &c1);
    g_rope[idx] = make_float4(c0, s0, c1, s1);
}

// ---------------- HMMA GEMM: C(128x128) = A(128xE) * W(128xE)^T, bf16 3-term split ----------------
// z = 0: Q (bias+rope, scatter)  1: K (same)  2: V (bias, scatter)  3: G (silu)  4: Wo (bias -> Cout)
__global__ __launch_bounds__(256, 1) void tc_gemm(
    const __nv_bfloat16* __restrict__ Ah, const __nv_bfloat16* __restrict__ Al,
    const float* __restrict__ b0, const float* __restrict__ b1,
    const float* __restrict__ b2, const float* __restrict__ b3,
    float* __restrict__ Cout, int single_mode)
{
    extern __shared__ __align__(16) char smem[];
    const int z = (single_mode >= 0) ? 4 : blockIdx.z;
    const float* bias = (z==1) ? b1 : (z==2) ? b2 : (z==3) ? b3 : b0;
    const __nv_bfloat16* Wh = g_Wh + (size_t)z * (E_*E_);
    const __nv_bfloat16* Wl = g_Wl + (size_t)z * (E_*E_);
    const int bm = blockIdx.y * 128, bn = blockIdx.x * 128;
    const int tid = threadIdx.x, wid = tid >> 5, lane = tid & 31;
    const int warp_m = wid >> 2, warp_n = wid & 3;
    const uint32_t sbase = smem_u32(smem);

    float c[4][4][4];
    #pragma unroll
    for (int i = 0; i < 4; ++i)
        #pragma unroll
        for (int j = 0; j < 4; ++j)
            #pragma unroll
            for (int r = 0; r < 4; ++r) c[i][j][r] = 0.f;

    // precompute per-thread loader coords
    int l_tile[8], l_row[8], l_seg[8];
    #pragma unroll
    for (int q = 0; q < 8; ++q) {
        const int ch = tid + q*256;
        l_tile[q] = ch >> 9;
        l_row[q]  = (ch & 511) >> 2;
        l_seg[q]  = (ch & 3) * 16;
    }

    #define ISSUE(s) do { \
        const uint32_t dstbuf = sbase + (uint32_t)((s)&1)*BUF_BYTES; \
        _Pragma("unroll") \
        for (int q = 0; q < 8; ++q) { \
            const __nv_bfloat16* bsrc = (l_tile[q]==0)?Ah:(l_tile[q]==1)?Al:(l_tile[q]==2)?Wh:Wl; \
            const int rowbase = (l_tile[q]<2)?bm:bn; \
            const char* src = (const char*)(bsrc + (size_t)(rowbase+l_row[q])*E_ + (s)*32) + l_seg[q]; \
            CPA16(dstbuf + l_tile[q]*TILE_BYTES + l_row[q]*TSTRIDE + l_seg[q], src); \
        } \
        CPA_COMMIT(); \
    } while(0)

    ISSUE(0);
    const int lrow15 = lane & 15;
    const uint32_t kseg = (lane >> 4) * 16;   // byte offset within k16

    for (int s = 0; s < 32; ++s) {
        if (s + 1 < 32) { ISSUE(s+1); CPA_WAIT(1); } else { CPA_WAIT(0); }
        __syncthreads();
        const uint32_t buf = sbase + (uint32_t)(s&1)*BUF_BYTES;
        #pragma unroll
        for (int k16 = 0; k16 < 2; ++k16) {
            const uint32_t koff = k16*32 + kseg;
            uint32_t bh[4][2], bl[4][2];
            #pragma unroll
            for (int p = 0; p < 2; ++p) {
                const int n = warp_n*32 + p*16 + lrow15;
                uint32_t r[4];
                ldsm4(r, buf + 2*TILE_BYTES + n*TSTRIDE + koff);
                bh[2*p][0]=r[0]; bh[2*p][1]=r[2]; bh[2*p+1][0]=r[1]; bh[2*p+1][1]=r[3];
                ldsm4(r, buf + 3*TILE_BYTES + n*TSTRIDE + koff);
                bl[2*p][0]=r[0]; bl[2*p][1]=r[2]; bl[2*p+1][0]=r[1]; bl[2*p+1][1]=r[3];
            }
            #pragma unroll
            for (int mf = 0; mf < 4; ++mf) {
                const int m = warp_m*64 + mf*16 + lrow15;
                uint32_t ah[4], al[4];
                ldsm4(ah, buf + 0*TILE_BYTES + m*TSTRIDE + koff);
                ldsm4(al, buf + 1*TILE_BYTES + m*TSTRIDE + koff);
                #pragma unroll
                for (int nf = 0; nf < 4; ++nf) {
                    mma16816(c[mf][nf], ah, bh[nf]);
                    mma16816(c[mf][nf], ah, bl[nf]);
                    mma16816(c[mf][nf], al, bh[nf]);
                }
            }
        }
        __syncthreads();
    }

    // ---------------- epilogue ----------------
    const int tq = lane >> 2, tr = lane & 3;
    #pragma unroll
    for (int mf = 0; mf < 4; ++mf) {
        #pragma unroll
        for (int nf = 0; nf < 4; ++nf) {
            #pragma unroll
            for (int half = 0; half < 2; ++half) {
                const int m = bm + warp_m*64 + mf*16 + tq + half*8;
                const int n0 = bn + warp_n*32 + nf*8 + tr*2;
                float v0 = c[mf][nf][half*2 + 0] + bias[n0];
                float v1 = c[mf][nf][half*2 + 1] + bias[n0 + 1];
                const int bb = m >> 11, t = m & 2047;
                if (z <= 2) {
                    const int h = n0 >> 6, hd = n0 & 63;
                    float* dst = ((z==0) ? g_Q : (z==1) ? g_K : g_V)
                                 + (((size_t)(bb*H_ + h) * T_ + t) * HD_) + hd;
                    if (z <= 1) {
                        const float4 cs = g_rope[(size_t)t*32 + (hd >> 1)];
                        const float o0 = v0*cs.x - v1*cs.y;
                        const float o1 = v1*cs.z + v0*cs.w;
                        *(float2*)dst = make_float2(o0, o1);
                    } else {
                        *(float2*)dst = make_float2(v0, v1);
                    }
                } else if (z == 3) {
                    g_G[(size_t)m*E_ + n0]     = v0 / (1.f + __expf(-v0));
                    g_G[(size_t)m*E_ + n0 + 1] = v1 / (1.f + __expf(-v1));
                } else {
                    *(float2*)(Cout + (size_t)m*E_ + n0) = make_float2(v0, v1);
                }
            }
        }
    }
}

// ---------------- Pass 1: backward chunk-state scan ----------------
__global__ __launch_bounds__(256) void ret_state_kernel()
{
    __shared__ float Ks[64][64];
    __shared__ float Vs[64][16];
    __shared__ float dec_s[65];

    const int eb = blockIdx.x, bh = blockIdx.y, h = bh & 15;
    const int tid = threadIdx.x;
    const int d = tid >> 2, eq = (tid & 3) * 4, e0 = eb * 16;

    if (tid < 65) dec_s[tid] = g_decay[h*T_ + tid];

    const float* Kg = g_K + (size_t)bh * T_ * HD_;
    const float* Vg = g_V + (size_t)bh * T_ * HD_;
    float* Rg = g_R + (size_t)bh * NT_ * (HD_*HD_);
    const int lrow = tid >> 2, lseg = (tid & 3) * 16;

    float R0=0.f, R1=0.f, R2=0.f, R3=0.f;
    *(float4*)&Rg[((NT_-1)*64 + d)*64 + e0 + eq] = make_float4(0.f,0.f,0.f,0.f);
    __syncthreads();
    const float gL = dec_s[64];

    for (int cc = NT_-1; cc >= 1; --cc) {
        const int j0 = cc * 64;
        {
            const float4* ks = (const float4*)(Kg + (size_t)(j0+lrow)*64 + lseg);
            float4* kd = (float4*)(&Ks[lrow][lseg]);
            #pragma unroll
            for (int q = 0; q < 4; ++q) kd[q] = ks[q];
            *(float4*)&Vs[lrow][(tid&3)*4] = *(const float4*)(Vg + (size_t)(j0+lrow)*64 + e0 + (tid&3)*4);
        }
        __syncthreads();
        float a0=0.f,a1=0.f,a2=0.f,a3=0.f;
        #pragma unroll 8
        for (int i = 0; i < 64; ++i) {
            const float kw = Ks[i][d] * dec_s[i];
            const float4 v = *(const float4*)&Vs[i][eq];
            a0 = fmaf(kw, v.x, a0); a1 = fmaf(kw, v.y, a1);
            a2 = fmaf(kw, v.z, a2); a3 = fmaf(kw, v.w, a3);
        }
        R0 = a0 + gL*R0; R1 = a1 + gL*R1; R2 = a2 + gL*R2; R3 = a3 + gL*R3;
        *(float4*)&Rg[((cc-1)*64 + d)*64 + e0 + eq] = make_float4(R0,R1,R2,R3);
        __syncthreads();
    }
}

// ---------------- Pass 2: intra-chunk + cross-chunk ----------------
__global__ __launch_bounds__(256) void ret_attn_kernel()
{
    __shared__ float Qs[64][64];
    __shared__ float KS[64][64];
    __shared__ float Vs[64][64];

    const int bh = blockIdx.y, b = bh >> 4, h = bh & 15;
    const int cI = blockIdx.x, q0 = cI * 64;

    const float* Qg = g_Q + (size_t)bh * T_ * HD_;
    const float* Kg = g_K + (size_t)bh * T_ * HD_;
    const float* Vg = g_V + (size_t)bh * T_ * HD_;
    const float* dec = g_decay + h * T_;
    const float* Rg = g_R + ((size_t)bh * NT_ + cI) * (HD_*HD_);

    const int tid = threadIdx.x;
    const int tx = tid & 15, ty = tid >> 4;
    const int lrow = tid >> 2, lseg = (tid & 3) * 16;

    {
        const float4* qsrc = (const float4*)(Qg + (size_t)(q0+lrow)*64 + lseg);
        float4* qdst = (float4*)(&Qs[lrow][lseg]);
        #pragma unroll
        for (int q = 0; q < 4; ++q) qdst[q] = qsrc[q];
        float4 k4[4];
        const float4* ks = (const float4*)(Kg + (size_t)(q0+lrow)*64 + lseg);
        #pragma unroll
        for (int q = 0; q < 4; ++q) k4[q] = ks[q];
        #pragma unroll
        for (int q = 0; q < 4; ++q) {
            KS[lseg+q*4+0][lrow] = k4[q].x; KS[lseg+q*4+1][lrow] = k4[q].y;
            KS[lseg+q*4+2][lrow] = k4[q].z; KS[lseg+q*4+3][lrow] = k4[q].w;
        }
        const float4* vs = (const float4*)(Vg + (size_t)(q0+lrow)*64 + lseg);
        float4* vd = (float4*)(&Vs[lrow][lseg]);
        #pragma unroll
        for (int q = 0; q < 4; ++q) vd[q] = vs[q];
    }
    __syncthreads();

    const float invsc = 0.125f;
    float s[4][4];
    #pragma unroll
    for (int i = 0; i < 4; ++i)
        #pragma unroll
        for (int j = 0; j < 4; ++j) s[i][j] = 0.f;

    #pragma unroll 8
    for (int k = 0; k < 64; ++k) {
        float4 kv = *(const float4*)(&KS[k][tx*4]);
        float qv[4];
        #pragma unroll
        for (int i = 0; i < 4; ++i) qv[i] = Qs[ty*4+i][k];
        #pragma unroll
        for (int i = 0; i < 4; ++i) {
            s[i][0] = fmaf(qv[i], kv.x, s[i][0]); s[i][1] = fmaf(qv[i], kv.y, s[i][1]);
            s[i][2] = fmaf(qv[i], kv.z, s[i][2]); s[i][3] = fmaf(qv[i], kv.w, s[i][3]);
        }
    }
    #pragma unroll
    for (int i = 0; i < 4; ++i) {
        const int ii = ty*4 + i;
        #pragma unroll
        for (int j = 0; j < 4; ++j) {
            const int jj = tx*4 + j;
            s[i][j] = (jj >= ii) ? s[i][j] * invsc * dec[jj-ii] : 0.f;
        }
    }
    __syncthreads();
    #pragma unroll
    for (int i = 0; i < 4; ++i)
        *(float4*)(&KS[ty*4+i][tx*4]) = make_float4(s[i][0], s[i][1], s[i][2], s[i][3]);
    __syncthreads();

    float o[4][4];
    #pragma unroll
    for (int i = 0; i < 4; ++i)
        #pragma unroll
        for (int j = 0; j < 4; ++j) o[i][j] = 0.f;

    #pragma unroll 8
    for (int k = 0; k < 64; ++k) {
        float4 vv = *(const float4*)(&Vs[k][tx*4]);
        float sv[4];
        #pragma unroll
        for (int i = 0; i < 4; ++i) sv[i] = KS[ty*4+i][k];
        #pragma unroll
        for (int i = 0; i < 4; ++i) {
            o[i][0] = fmaf(sv[i], vv.x, o[i][0]); o[i][1] = fmaf(sv[i], vv.y, o[i][1]);
            o[i][2] = fmaf(sv[i], vv.z, o[i][2]); o[i][3] = fmaf(sv[i], vv.w, o[i][3]);
        }
    }

    float cr[4][4];
    #pragma unroll
    for (int i = 0; i < 4; ++i)
        #pragma unroll
        for (int j = 0; j < 4; ++j) cr[i][j] = 0.f;
    #pragma unroll 4
    for (int d = 0; d < 64; ++d) {
        const float4 rv = __ldg((const float4*)&Rg[d*64 + tx*4]);
        float qd[4];
        #pragma unroll
        for (int i = 0; i < 4; ++i) qd[i] = Qs[ty*4+i][d];
        #pragma unroll
        for (int i = 0; i < 4; ++i) {
            cr[i][0] = fmaf(qd[i], rv.x, cr[i][0]); cr[i][1] = fmaf(qd[i], rv.y, cr[i][1]);
            cr[i][2] = fmaf(qd[i], rv.z, cr[i][2]); cr[i][3] = fmaf(qd[i], rv.w, cr[i][3]);
        }
    }
    #pragma unroll
    for (int i = 0; i < 4; ++i) {
        const int ii = ty*4 + i;
        const float coef = invsc * dec[64 - ii];
        #pragma unroll
        for (int j = 0; j < 4; ++j) o[i][j] = fmaf(coef, cr[i][j], o[i][j]);
    }
    #pragma unroll
    for (int i = 0; i < 4; ++i) {
        const int t = q0 + ty*4 + i;
        float* dst = g_O + ((size_t)(b*T_ + t)) * E_ + h*64 + tx*4;
        *(float4*)dst = make_float4(o[i][0], o[i][1], o[i][2], o[i][3]);
    }
}

// ---------------- GroupNorm + gate -> bf16 split for Wo GEMM ----------------
__global__ __launch_bounds__(256) void gn_kernel(
    const float* __restrict__ gn_w, const float* __restrict__ gn_b)
{
    const int bh = blockIdx.x;
    const int b = bh >> 4, h = bh & 15;
    const size_t base = (size_t)b * T_ * E_ + h * 64;

    double sum = 0.0, sumsq = 0.0;
    for (int i = threadIdx.x; i < T_*64; i += 256) {
        const int t = i >> 6, hd = i & 63;
        const float v = g_O[base + (size_t)t * E_ + hd];
        sum += v; sumsq += (double)v * (double)v;
    }
    __shared__ double ssum[256], ssq[256];
    ssum[threadIdx.x] = sum; ssq[threadIdx.x] = sumsq;
    __syncthreads();
    for (int off = 128; off > 0; off >>= 1) {
        if (threadIdx.x < off) { ssum[threadIdx.x] += ssum[threadIdx.x+off]; ssq[threadIdx.x] += ssq[threadIdx.x+off]; }
        __syncthreads();
    }
    const double N = (double)(T_*64);
    const double mu = ssum[0] / N;
    const double var = ssq[0] / N - mu*mu;
    const float muf = (float)mu;
    const float rs = (float)(1.0 / sqrt(var + 1e-5));

    for (int i = threadIdx.x; i < T_*64; i += 256) {
        const int t = i >> 6, hd = i & 63;
        const int e = h*64 + hd;
        const size_t idx = (size_t)(b*T_ + t) * E_ + e;
        const float v = (g_O[idx] - muf) * rs * gn_w[e] + gn_b[e];
        const float out = v * g_G[idx];
        const __nv_bfloat16 hh = __float2bfloat16(out);
        g_Ah[idx] = hh;
        g_Al[idx] = __float2bfloat16(out - __bfloat162float(hh));
    }
}

// ---------------- launch ----------------
extern "C" void kernel_launch(void* const* d_in, const int* in_sizes, int n_in,
                              void* d_out, int out_size)
{
    const float* x    = (const float*)d_in[0];
    const float* Wq   = (const float*)d_in[1];
    const float* bq   = (const float*)d_in[2];
    const float* Wk   = (const float*)d_in[3];
    const float* bk   = (const float*)d_in[4];
    const float* Wv   = (const float*)d_in[5];
    const float* bv   = (const float*)d_in[6];
    const float* Wg   = (const float*)d_in[7];
    const float* bg   = (const float*)d_in[8];
    const float* Wo   = (const float*)d_in[9];
    const float* bo   = (const float*)d_in[10];
    const float* gn_w = (const float*)d_in[11];
    const float* gn_b = (const float*)d_in[12];

    __nv_bfloat16 *Ah, *Al, *Wh, *Wl;
    cudaGetSymbolAddress((void**)&Ah, g_Ah);
    cudaGetSymbolAddress((void**)&Al, g_Al);
    cudaGetSymbolAddress((void**)&Wh, g_Wh);
    cudaGetSymbolAddress((void**)&Wl, g_Wl);

    cudaFuncSetAttribute(tc_gemm, cudaFuncAttributeMaxDynamicSharedMemorySize, DYN_SMEM);

    decay_kernel<<<(H_*T_ + 255)/256, 256>>>();
    rope_table_kernel<<<(T_*32 + 255)/256, 256>>>();

    const int nx = M_*E_, nw = E_*E_;
    split_kernel<<<(nx + 255)/256, 256>>>(x,  Ah, Al, nx);
    split_kernel<<<(nw + 255)/256, 256>>>(Wq, Wh + 0*nw, Wl + 0*nw, nw);
    split_kernel<<<(nw + 255)/256, 256>>>(Wk, Wh + 1*nw, Wl + 1*nw, nw);
    split_kernel<<<(nw + 255)/256, 256>>>(Wv, Wh + 2*nw, Wl + 2*nw, nw);
    split_kernel<<<(nw + 255)/256, 256>>>(Wg, Wh + 3*nw, Wl + 3*nw, nw);
    split_kernel<<<(nw + 255)/256, 256>>>(Wo, Wh + 4*nw, Wl + 4*nw, nw);

    // fused Q,K,V,G projections (rope/scatter/silu in epilogue)
    tc_gemm<<<dim3(E_/128, M_/128, 4), 256, DYN_SMEM>>>(Ah, Al, bq, bk, bv, bg, nullptr, -1);

    ret_state_kernel<<<dim3(4, B_*H_), 256>>>();
    ret_attn_kernel<<<dim3(NT_, B_*H_), 256>>>();

    gn_kernel<<<B_*H_, 256>>>(gn_w, gn_b);

    // final output GEMM (reads GN split from g_Ah/g_Al)
    tc_gemm<<<dim3(E_/128, M_/128, 1), 256, DYN_SMEM>>>(Ah, Al, bo, nullptr, nullptr, nullptr,
                                                        (float*)d_out, 4);
}

// round 7
// speedup vs baseline: 2.3318x; 1.0940x over previous
#include <cuda_runtime.h>
#include <cuda_bf16.h>
#include <math.h>
#include <stdint.h>

#define B_  2
#define T_  2048
#define E_  1024
#define H_  16
#define HD_ 64
#define M_  (B_*T_)
#define NT_ (T_/64)

#define TSTRIDE 80                   // bytes per smem tile row (32 bf16 + 8 pad)
#define TILE_BYTES (128*TSTRIDE)     // 10240
#define BUF_BYTES (4*TILE_BYTES)     // 40960
#define NSTAGE 3
#define DYN_SMEM (NSTAGE*BUF_BYTES)  // 122880

// ---------------- scratch ----------------
__device__ float g_Q[B_*H_*T_*HD_];
__device__ float g_K[B_*H_*T_*HD_];
__device__ float g_V[B_*H_*T_*HD_];
__device__ float g_G[B_*T_*E_];
__device__ float g_O[B_*T_*E_];
__device__ float g_decay[H_*T_];
__device__ float g_R[B_*H_*NT_*HD_*HD_];
__device__ float4 g_rope[T_*32];
__device__ __nv_bfloat16 g_Ah[M_*E_], g_Al[M_*E_];
__device__ __nv_bfloat16 g_Wh[5*E_*E_], g_Wl[5*E_*E_];

// ---------------- helpers ----------------
__device__ __forceinline__ uint32_t smem_u32(const void* p){
    uint32_t a; asm("{ .reg .u64 t; cvta.to.shared.u64 t, %1; cvt.u32.u64 %0, t; }":"=r"(a):"l"(p)); return a;
}
__device__ __forceinline__ void ldsm4(uint32_t r[4], uint32_t a){
    asm volatile("ldmatrix.sync.aligned.m8n8.x4.shared.b16 {%0,%1,%2,%3}, [%4];"
        :"=r"(r[0]),"=r"(r[1]),"=r"(r[2]),"=r"(r[3]):"r"(a));
}
__device__ __forceinline__ void mma16816(float c[4], const uint32_t a[4], const uint32_t b[2]){
    asm volatile("mma.sync.aligned.m16n8k16.row.col.f32.bf16.bf16.f32 "
        "{%0,%1,%2,%3}, {%4,%5,%6,%7}, {%8,%9}, {%0,%1,%2,%3};"
        : "+f"(c[0]),"+f"(c[1]),"+f"(c[2]),"+f"(c[3])
        : "r"(a[0]),"r"(a[1]),"r"(a[2]),"r"(a[3]),"r"(b[0]),"r"(b[1]));
}
#define CPA16(dst, src)  asm volatile("cp.async.cg.shared.global [%0], [%1], 16;"::"r"(dst),"l"(src))
#define CPA_COMMIT()     asm volatile("cp.async.commit_group;":::"memory")
#define CPA_WAIT1()      asm volatile("cp.async.wait_group 1;":::"memory")
#define CPA_WAIT0()      asm volatile("cp.async.wait_group 0;":::"memory")

// ---------------- prep: fused split of x + 5 weights into bf16 hi/lo ----------------
__global__ void split_all_kernel(const float* __restrict__ x,
    const float* __restrict__ Wq, const float* __restrict__ Wk,
    const float* __restrict__ Wv, const float* __restrict__ Wg,
    const float* __restrict__ Wo)
{
    const int i = blockIdx.x*256 + threadIdx.x;
    const int NX = M_*E_;                      // 4M
    float v; __nv_bfloat16 *hi, *lo;
    if (i < NX) {
        v = x[i]; hi = g_Ah + i; lo = g_Al + i;
    } else {
        const int j = i - NX;                  // < 5M
        const int w = j >> 20, off = j & ((1<<20)-1);
        const float* src = (w==0)?Wq:(w==1)?Wk:(w==2)?Wv:(w==3)?Wg:Wo;
        v = src[off]; hi = g_Wh + j; lo = g_Wl + j;
    }
    const __nv_bfloat16 h = __float2bfloat16(v);
    *hi = h; *lo = __float2bfloat16(v - __bfloat162float(h));
}

__global__ void decay_kernel()
{
    const int idx = blockIdx.x*256 + threadIdx.x;
    if (idx >= H_*T_) return;
    const int h = idx >> 11, d = idx & 2047;
    const double gamma = 1.0 - exp2(-(double)(5 + h));
    g_decay[idx] = (float)pow(gamma, (double)d);
}

__global__ void rope_table_kernel()
{
    int idx = blockIdx.x*256 + threadIdx.x;
    if (idx >= T_*32) return;
    int t = idx >> 5, p = idx & 31;
    float inv0 = (float)pow(10000.0, -(double)((2*p)   & 31) / 32.0);
    float inv1 = (float)pow(10000.0, -(double)((2*p+1) & 31) / 32.0);
    float s0,c0,s1,c1;
    sincosf((float)t * inv0, &s0, &c0);
    sincosf((float)t * inv1, &s1, &c1);
    g_rope[idx] = make_float4(c0, s0, c1, s1);
}

// ---------------- HMMA GEMM: C(128x128) = A(128xE) * W(128xE)^T, bf16 3-term split ----------------
// z = 0: Q (bias+rope, scatter)  1: K (same)  2: V (bias, scatter)  3: G (silu)  4: Wo -> Cout
__global__ __launch_bounds__(256, 1) void tc_gemm(
    const __nv_bfloat16* __restrict__ Ah, const __nv_bfloat16* __restrict__ Al,
    const float* __restrict__ b0, const float* __restrict__ b1,
    const float* __restrict__ b2, const float* __restrict__ b3,
    float* __restrict__ Cout, int single_mode)
{
    extern __shared__ __align__(16) char smem[];
    const int z = (single_mode >= 0) ? 4 : blockIdx.z;
    const float* bias = (z==1) ? b1 : (z==2) ? b2 : (z==3) ? b3 : b0;
    const __nv_bfloat16* Wh = g_Wh + (size_t)z * (E_*E_);
    const __nv_bfloat16* Wl = g_Wl + (size_t)z * (E_*E_);
    const int bm = blockIdx.y * 128, bn = blockIdx.x * 128;
    const int tid = threadIdx.x, wid = tid >> 5, lane = tid & 31;
    const int warp_m = wid >> 2, warp_n = wid & 3;
    const uint32_t sbase = smem_u32(smem);

    float c[4][4][4];
    #pragma unroll
    for (int i = 0; i < 4; ++i)
        #pragma unroll
        for (int j = 0; j < 4; ++j)
            #pragma unroll
            for (int r = 0; r < 4; ++r) c[i][j][r] = 0.f;

    // precomputed loader pointers (advance 64B per slab)
    const char* srcp[8];
    uint32_t dsto[8];
    #pragma unroll
    for (int q = 0; q < 8; ++q) {
        const int ch = tid + q*256;
        const int tile = ch >> 9, row = (ch & 511) >> 2, seg = (ch & 3) * 16;
        const __nv_bfloat16* base = (tile==0)?Ah:(tile==1)?Al:(tile==2)?Wh:Wl;
        const int rowbase = (tile < 2) ? bm : bn;
        srcp[q] = (const char*)(base + (size_t)(rowbase + row)*E_) + seg;
        dsto[q] = (uint32_t)(tile*TILE_BYTES + row*TSTRIDE + seg);
    }

    #define ISSUE(s) do { \
        const uint32_t dstbuf = sbase + (uint32_t)((s)%NSTAGE)*BUF_BYTES; \
        const size_t soff = (size_t)(s)*64; \
        _Pragma("unroll") \
        for (int q = 0; q < 8; ++q) CPA16(dstbuf + dsto[q], srcp[q] + soff); \
        CPA_COMMIT(); \
    } while(0)

    ISSUE(0); ISSUE(1);
    const int lrow15 = lane & 15;
    const uint32_t kseg = (lane >> 4) * 16;

    for (int s = 0; s < 32; ++s) {
        if (s < 31) CPA_WAIT1(); else CPA_WAIT0();
        __syncthreads();
        if (s + 2 < 32) ISSUE(s + 2);
        const uint32_t buf = sbase + (uint32_t)(s % NSTAGE)*BUF_BYTES;
        #pragma unroll
        for (int k16 = 0; k16 < 2; ++k16) {
            const uint32_t koff = k16*32 + kseg;
            uint32_t bh[4][2], bl[4][2];
            #pragma unroll
            for (int p = 0; p < 2; ++p) {
                const int n = warp_n*32 + p*16 + lrow15;
                uint32_t r[4];
                ldsm4(r, buf + 2*TILE_BYTES + n*TSTRIDE + koff);
                bh[2*p][0]=r[0]; bh[2*p][1]=r[2]; bh[2*p+1][0]=r[1]; bh[2*p+1][1]=r[3];
                ldsm4(r, buf + 3*TILE_BYTES + n*TSTRIDE + koff);
                bl[2*p][0]=r[0]; bl[2*p][1]=r[2]; bl[2*p+1][0]=r[1]; bl[2*p+1][1]=r[3];
            }
            #pragma unroll
            for (int mf = 0; mf < 4; ++mf) {
                const int m = warp_m*64 + mf*16 + lrow15;
                uint32_t ah[4], al[4];
                ldsm4(ah, buf + 0*TILE_BYTES + m*TSTRIDE + koff);
                ldsm4(al, buf + 1*TILE_BYTES + m*TSTRIDE + koff);
                #pragma unroll
                for (int nf = 0; nf < 4; ++nf) {
                    mma16816(c[mf][nf], ah, bh[nf]);
                    mma16816(c[mf][nf], ah, bl[nf]);
                    mma16816(c[mf][nf], al, bh[nf]);
                }
            }
        }
    }

    // ---------------- epilogue ----------------
    const int tq = lane >> 2, tr = lane & 3;
    #pragma unroll
    for (int mf = 0; mf < 4; ++mf) {
        #pragma unroll
        for (int nf = 0; nf < 4; ++nf) {
            #pragma unroll
            for (int half = 0; half < 2; ++half) {
                const int m = bm + warp_m*64 + mf*16 + tq + half*8;
                const int n0 = bn + warp_n*32 + nf*8 + tr*2;
                float v0 = c[mf][nf][half*2 + 0] + bias[n0];
                float v1 = c[mf][nf][half*2 + 1] + bias[n0 + 1];
                const int bb = m >> 11, t = m & 2047;
                if (z <= 2) {
                    const int h = n0 >> 6, hd = n0 & 63;
                    float* dst = ((z==0) ? g_Q : (z==1) ? g_K : g_V)
                                 + (((size_t)(bb*H_ + h) * T_ + t) * HD_) + hd;
                    if (z <= 1) {
                        const float4 cs = g_rope[(size_t)t*32 + (hd >> 1)];
                        *(float2*)dst = make_float2(v0*cs.x - v1*cs.y, v1*cs.z + v0*cs.w);
                    } else {
                        *(float2*)dst = make_float2(v0, v1);
                    }
                } else if (z == 3) {
                    g_G[(size_t)m*E_ + n0]     = v0 / (1.f + __expf(-v0));
                    g_G[(size_t)m*E_ + n0 + 1] = v1 / (1.f + __expf(-v1));
                } else {
                    *(float2*)(Cout + (size_t)m*E_ + n0) = make_float2(v0, v1);
                }
            }
        }
    }
    #undef ISSUE
}

// ---------------- Pass 1: backward chunk-state scan ----------------
__global__ __launch_bounds__(256) void ret_state_kernel()
{
    __shared__ float Ks[64][64];
    __shared__ float Vs[64][16];
    __shared__ float dec_s[65];

    const int eb = blockIdx.x, bh = blockIdx.y, h = bh & 15;
    const int tid = threadIdx.x;
    const int d = tid >> 2, eq = (tid & 3) * 4, e0 = eb * 16;

    if (tid < 65) dec_s[tid] = g_decay[h*T_ + tid];

    const float* Kg = g_K + (size_t)bh * T_ * HD_;
    const float* Vg = g_V + (size_t)bh * T_ * HD_;
    float* Rg = g_R + (size_t)bh * NT_ * (HD_*HD_);
    const int lrow = tid >> 2, lseg = (tid & 3) * 16;

    float R0=0.f, R1=0.f, R2=0.f, R3=0.f;
    *(float4*)&Rg[((NT_-1)*64 + d)*64 + e0 + eq] = make_float4(0.f,0.f,0.f,0.f);
    __syncthreads();
    const float gL = dec_s[64];

    for (int cc = NT_-1; cc >= 1; --cc) {
        const int j0 = cc * 64;
        {
            const float4* ks = (const float4*)(Kg + (size_t)(j0+lrow)*64 + lseg);
            float4* kd = (float4*)(&Ks[lrow][lseg]);
            #pragma unroll
            for (int q = 0; q < 4; ++q) kd[q] = ks[q];
            *(float4*)&Vs[lrow][(tid&3)*4] = *(const float4*)(Vg + (size_t)(j0+lrow)*64 + e0 + (tid&3)*4);
        }
        __syncthreads();
        float a0=0.f,a1=0.f,a2=0.f,a3=0.f;
        #pragma unroll 8
        for (int i = 0; i < 64; ++i) {
            const float kw = Ks[i][d] * dec_s[i];
            const float4 v = *(const float4*)&Vs[i][eq];
            a0 = fmaf(kw, v.x, a0); a1 = fmaf(kw, v.y, a1);
            a2 = fmaf(kw, v.z, a2); a3 = fmaf(kw, v.w, a3);
        }
        R0 = a0 + gL*R0; R1 = a1 + gL*R1; R2 = a2 + gL*R2; R3 = a3 + gL*R3;
        *(float4*)&Rg[((cc-1)*64 + d)*64 + e0 + eq] = make_float4(R0,R1,R2,R3);
        __syncthreads();
    }
}

// ---------------- Pass 2: intra-chunk + cross-chunk ----------------
__global__ __launch_bounds__(256) void ret_attn_kernel()
{
    __shared__ float Qs[64][64];
    __shared__ float KS[64][64];
    __shared__ float Vs[64][64];

    const int bh = blockIdx.y, b = bh >> 4, h = bh & 15;
    const int cI = blockIdx.x, q0 = cI * 64;

    const float* Qg = g_Q + (size_t)bh * T_ * HD_;
    const float* Kg = g_K + (size_t)bh * T_ * HD_;
    const float* Vg = g_V + (size_t)bh * T_ * HD_;
    const float* dec = g_decay + h * T_;
    const float* Rg = g_R + ((size_t)bh * NT_ + cI) * (HD_*HD_);

    const int tid = threadIdx.x;
    const int tx = tid & 15, ty = tid >> 4;
    const int lrow = tid >> 2, lseg = (tid & 3) * 16;

    {
        const float4* qsrc = (const float4*)(Qg + (size_t)(q0+lrow)*64 + lseg);
        float4* qdst = (float4*)(&Qs[lrow][lseg]);
        #pragma unroll
        for (int q = 0; q < 4; ++q) qdst[q] = qsrc[q];
        float4 k4[4];
        const float4* ks = (const float4*)(Kg + (size_t)(q0+lrow)*64 + lseg);
        #pragma unroll
        for (int q = 0; q < 4; ++q) k4[q] = ks[q];
        #pragma unroll
        for (int q = 0; q < 4; ++q) {
            KS[lseg+q*4+0][lrow] = k4[q].x; KS[lseg+q*4+1][lrow] = k4[q].y;
            KS[lseg+q*4+2][lrow] = k4[q].z; KS[lseg+q*4+3][lrow] = k4[q].w;
        }
        const float4* vs = (const float4*)(Vg + (size_t)(q0+lrow)*64 + lseg);
        float4* vd = (float4*)(&Vs[lrow][lseg]);
        #pragma unroll
        for (int q = 0; q < 4; ++q) vd[q] = vs[q];
    }
    __syncthreads();

    const float invsc = 0.125f;
    float s[4][4];
    #pragma unroll
    for (int i = 0; i < 4; ++i)
        #pragma unroll
        for (int j = 0; j < 4; ++j) s[i][j] = 0.f;

    #pragma unroll 8
    for (int k = 0; k < 64; ++k) {
        float4 kv = *(const float4*)(&KS[k][tx*4]);
        float qv[4];
        #pragma unroll
        for (int i = 0; i < 4; ++i) qv[i] = Qs[ty*4+i][k];
        #pragma unroll
        for (int i = 0; i < 4; ++i) {
            s[i][0] = fmaf(qv[i], kv.x, s[i][0]); s[i][1] = fmaf(qv[i], kv.y, s[i][1]);
            s[i][2] = fmaf(qv[i], kv.z, s[i][2]); s[i][3] = fmaf(qv[i], kv.w, s[i][3]);
        }
    }
    #pragma unroll
    for (int i = 0; i < 4; ++i) {
        const int ii = ty*4 + i;
        #pragma unroll
        for (int j = 0; j < 4; ++j) {
            const int jj = tx*4 + j;
            s[i][j] = (jj >= ii) ? s[i][j] * invsc * dec[jj-ii] : 0.f;
        }
    }
    __syncthreads();
    #pragma unroll
    for (int i = 0; i < 4; ++i)
        *(float4*)(&KS[ty*4+i][tx*4]) = make_float4(s[i][0], s[i][1], s[i][2], s[i][3]);
    __syncthreads();

    float o[4][4];
    #pragma unroll
    for (int i = 0; i < 4; ++i)
        #pragma unroll
        for (int j = 0; j < 4; ++j) o[i][j] = 0.f;

    #pragma unroll 8
    for (int k = 0; k < 64; ++k) {
        float4 vv = *(const float4*)(&Vs[k][tx*4]);
        float sv[4];
        #pragma unroll
        for (int i = 0; i < 4; ++i) sv[i] = KS[ty*4+i][k];
        #pragma unroll
        for (int i = 0; i < 4; ++i) {
            o[i][0] = fmaf(sv[i], vv.x, o[i][0]); o[i][1] = fmaf(sv[i], vv.y, o[i][1]);
            o[i][2] = fmaf(sv[i], vv.z, o[i][2]); o[i][3] = fmaf(sv[i], vv.w, o[i][3]);
        }
    }

    float cr[4][4];
    #pragma unroll
    for (int i = 0; i < 4; ++i)
        #pragma unroll
        for (int j = 0; j < 4; ++j) cr[i][j] = 0.f;
    #pragma unroll 4
    for (int d = 0; d < 64; ++d) {
        const float4 rv = __ldg((const float4*)&Rg[d*64 + tx*4]);
        float qd[4];
        #pragma unroll
        for (int i = 0; i < 4; ++i) qd[i] = Qs[ty*4+i][d];
        #pragma unroll
        for (int i = 0; i < 4; ++i) {
            cr[i][0] = fmaf(qd[i], rv.x, cr[i][0]); cr[i][1] = fmaf(qd[i], rv.y, cr[i][1]);
            cr[i][2] = fmaf(qd[i], rv.z, cr[i][2]); cr[i][3] = fmaf(qd[i], rv.w, cr[i][3]);
        }
    }
    #pragma unroll
    for (int i = 0; i < 4; ++i) {
        const int ii = ty*4 + i;
        const float coef = invsc * dec[64 - ii];
        #pragma unroll
        for (int j = 0; j < 4; ++j) o[i][j] = fmaf(coef, cr[i][j], o[i][j]);
    }
    #pragma unroll
    for (int i = 0; i < 4; ++i) {
        const int t = q0 + ty*4 + i;
        float* dst = g_O + ((size_t)(b*T_ + t)) * E_ + h*64 + tx*4;
        *(float4*)dst = make_float4(o[i][0], o[i][1], o[i][2], o[i][3]);
    }
}

// ---------------- GroupNorm + gate -> bf16 split for Wo GEMM (fp32 accum) ----------------
__global__ __launch_bounds__(256) void gn_kernel(
    const float* __restrict__ gn_w, const float* __restrict__ gn_b)
{
    const int bh = blockIdx.x;
    const int b = bh >> 4, h = bh & 15;
    const size_t base = (size_t)b * T_ * E_ + h * 64;

    float sum = 0.f, sumsq = 0.f;
    for (int i = threadIdx.x; i < T_*64; i += 256) {
        const int t = i >> 6, hd = i & 63;
        const float v = g_O[base + (size_t)t * E_ + hd];
        sum += v; sumsq = fmaf(v, v, sumsq);
    }
    __shared__ float ssum[256], ssq[256];
    ssum[threadIdx.x] = sum; ssq[threadIdx.x] = sumsq;
    __syncthreads();
    for (int off = 128; off > 0; off >>= 1) {
        if (threadIdx.x < off) { ssum[threadIdx.x] += ssum[threadIdx.x+off]; ssq[threadIdx.x] += ssq[threadIdx.x+off]; }
        __syncthreads();
    }
    const float N = (float)(T_*64);
    const float mu = ssum[0] / N;
    const float var = ssq[0] / N - mu*mu;
    const float rs = rsqrtf(var + 1e-5f);

    for (int i = threadIdx.x; i < T_*64; i += 256) {
        const int t = i >> 6, hd = i & 63;
        const int e = h*64 + hd;
        const size_t idx = (size_t)(b*T_ + t) * E_ + e;
        const float v = (g_O[idx] - mu) * rs * gn_w[e] + gn_b[e];
        const float out = v * g_G[idx];
        const __nv_bfloat16 hh = __float2bfloat16(out);
        g_Ah[idx] = hh;
        g_Al[idx] = __float2bfloat16(out - __bfloat162float(hh));
    }
}

// ---------------- launch ----------------
extern "C" void kernel_launch(void* const* d_in, const int* in_sizes, int n_in,
                              void* d_out, int out_size)
{
    const float* x    = (const float*)d_in[0];
    const float* Wq   = (const float*)d_in[1];
    const float* bq   = (const float*)d_in[2];
    const float* Wk   = (const float*)d_in[3];
    const float* bk   = (const float*)d_in[4];
    const float* Wv   = (const float*)d_in[5];
    const float* bv   = (const float*)d_in[6];
    const float* Wg   = (const float*)d_in[7];
    const float* bg   = (const float*)d_in[8];
    const float* Wo   = (const float*)d_in[9];
    const float* bo   = (const float*)d_in[10];
    const float* gn_w = (const float*)d_in[11];
    const float* gn_b = (const float*)d_in[12];

    __nv_bfloat16 *Ah, *Al;
    cudaGetSymbolAddress((void**)&Ah, g_Ah);
    cudaGetSymbolAddress((void**)&Al, g_Al);

    cudaFuncSetAttribute(tc_gemm, cudaFuncAttributeMaxDynamicSharedMemorySize, DYN_SMEM);

    decay_kernel<<<(H_*T_ + 255)/256, 256>>>();
    rope_table_kernel<<<(T_*32 + 255)/256, 256>>>();

    const int ntot = M_*E_ + 5*E_*E_;          // 9.4M
    split_all_kernel<<<(ntot + 255)/256, 256>>>(x, Wq, Wk, Wv, Wg, Wo);

    // fused Q,K,V,G projections (rope/scatter/silu in epilogue)
    tc_gemm<<<dim3(E_/128, M_/128, 4), 256, DYN_SMEM>>>(Ah, Al, bq, bk, bv, bg, nullptr, -1);

    ret_state_kernel<<<dim3(4, B_*H_), 256>>>();
    ret_attn_kernel<<<dim3(NT_, B_*H_), 256>>>();

    gn_kernel<<<B_*H_, 256>>>(gn_w, gn_b);

    // final output GEMM (reads GN split from g_Ah/g_Al)
    tc_gemm<<<dim3(E_/128, M_/128, 1), 256, DYN_SMEM>>>(Ah, Al, bo, nullptr, nullptr, nullptr,
                                                        (float*)d_out, 4);
}

// round 8
// speedup vs baseline: 3.6275x; 1.5557x over previous
#include <cuda_runtime.h>
#include <cuda_bf16.h>
#include <math.h>
#include <stdint.h>

#define B_  2
#define T_  2048
#define E_  1024
#define H_  16
#define HD_ 64
#define M_  (B_*T_)
#define NT_ (T_/64)

#define TSTRIDE 80                   // bytes per smem tile row (32 bf16 + 8 pad)
#define TILE_BYTES (128*TSTRIDE)     // 10240
#define BUF_BYTES (4*TILE_BYTES)     // 40960
#define NSTAGE 2
#define DYN_SMEM (NSTAGE*BUF_BYTES)  // 81920 -> 2 CTAs/SM

// ---------------- scratch ----------------
__device__ float g_Q[B_*H_*T_*HD_];
__device__ float g_K[B_*H_*T_*HD_];
__device__ float g_V[B_*H_*T_*HD_];
__device__ float g_G[B_*T_*E_];
__device__ float g_O[B_*T_*E_];
__device__ float g_decay[H_*T_];
__device__ float g_R[B_*H_*NT_*HD_*HD_];
__device__ float4 g_rope[T_*32];
__device__ float2 g_stat[B_*H_];
__device__ __nv_bfloat16 g_Ah[M_*E_], g_Al[M_*E_];
__device__ __nv_bfloat16 g_Wh[5*E_*E_], g_Wl[5*E_*E_];

// ---------------- helpers ----------------
__device__ __forceinline__ uint32_t smem_u32(const void* p){
    uint32_t a; asm("{ .reg .u64 t; cvta.to.shared.u64 t, %1; cvt.u32.u64 %0, t; }":"=r"(a):"l"(p)); return a;
}
__device__ __forceinline__ void ldsm4(uint32_t r[4], uint32_t a){
    asm volatile("ldmatrix.sync.aligned.m8n8.x4.shared.b16 {%0,%1,%2,%3}, [%4];"
        :"=r"(r[0]),"=r"(r[1]),"=r"(r[2]),"=r"(r[3]):"r"(a));
}
__device__ __forceinline__ void mma16816(float c[4], const uint32_t a[4], const uint32_t b[2]){
    asm volatile("mma.sync.aligned.m16n8k16.row.col.f32.bf16.bf16.f32 "
        "{%0,%1,%2,%3}, {%4,%5,%6,%7}, {%8,%9}, {%0,%1,%2,%3};"
        : "+f"(c[0]),"+f"(c[1]),"+f"(c[2]),"+f"(c[3])
        : "r"(a[0]),"r"(a[1]),"r"(a[2]),"r"(a[3]),"r"(b[0]),"r"(b[1]));
}
#define CPA16(dst, src)  asm volatile("cp.async.cg.shared.global [%0], [%1], 16;"::"r"(dst),"l"(src))
#define CPA_COMMIT()     asm volatile("cp.async.commit_group;":::"memory")
#define CPA_WAIT1()      asm volatile("cp.async.wait_group 1;":::"memory")
#define CPA_WAIT0()      asm volatile("cp.async.wait_group 0;":::"memory")

// ---------------- prep ----------------
__global__ void split_all_kernel(const float* __restrict__ x,
    const float* __restrict__ Wq, const float* __restrict__ Wk,
    const float* __restrict__ Wv, const float* __restrict__ Wg,
    const float* __restrict__ Wo)
{
    const int i = blockIdx.x*256 + threadIdx.x;
    const int NX = M_*E_;
    float v; __nv_bfloat16 *hi, *lo;
    if (i < NX) {
        v = x[i]; hi = g_Ah + i; lo = g_Al + i;
    } else {
        const int j = i - NX;
        const int w = j >> 20, off = j & ((1<<20)-1);
        const float* src = (w==0)?Wq:(w==1)?Wk:(w==2)?Wv:(w==3)?Wg:Wo;
        v = src[off]; hi = g_Wh + j; lo = g_Wl + j;
    }
    const __nv_bfloat16 h = __float2bfloat16(v);
    *hi = h; *lo = __float2bfloat16(v - __bfloat162float(h));
}

__global__ void decay_kernel()   // also zeroes gn stats
{
    const int idx = blockIdx.x*256 + threadIdx.x;
    if (idx < B_*H_) g_stat[idx] = make_float2(0.f, 0.f);
    if (idx >= H_*T_) return;
    const int h = idx >> 11, d = idx & 2047;
    const double gamma = 1.0 - exp2(-(double)(5 + h));
    g_decay[idx] = (float)pow(gamma, (double)d);
}

__global__ void rope_table_kernel()
{
    int idx = blockIdx.x*256 + threadIdx.x;
    if (idx >= T_*32) return;
    int t = idx >> 5, p = idx & 31;
    float inv0 = (float)pow(10000.0, -(double)((2*p)   & 31) / 32.0);
    float inv1 = (float)pow(10000.0, -(double)((2*p+1) & 31) / 32.0);
    float s0,c0,s1,c1;
    sincosf((float)t * inv0, &s0, &c0);
    sincosf((float)t * inv1, &s1, &c1);
    g_rope[idx] = make_float4(c0, s0, c1, s1);
}

// ---------------- HMMA GEMM 128x128 tile, bf16 3-term split, 2 CTAs/SM ----------------
__global__ __launch_bounds__(256, 2) void tc_gemm(
    const __nv_bfloat16* __restrict__ Ah, const __nv_bfloat16* __restrict__ Al,
    const float* __restrict__ b0, const float* __restrict__ b1,
    const float* __restrict__ b2, const float* __restrict__ b3,
    float* __restrict__ Cout, int single_mode)
{
    extern __shared__ __align__(16) char smem[];
    const int z = (single_mode >= 0) ? 4 : blockIdx.z;
    const float* bias = (z==1) ? b1 : (z==2) ? b2 : (z==3) ? b3 : b0;
    const __nv_bfloat16* Wh = g_Wh + (size_t)z * (E_*E_);
    const __nv_bfloat16* Wl = g_Wl + (size_t)z * (E_*E_);
    const int bm = blockIdx.y * 128, bn = blockIdx.x * 128;
    const int tid = threadIdx.x, wid = tid >> 5, lane = tid & 31;
    const int warp_m = wid >> 2, warp_n = wid & 3;
    const uint32_t sbase = smem_u32(smem);

    float c[4][4][4];
    #pragma unroll
    for (int i = 0; i < 4; ++i)
        #pragma unroll
        for (int j = 0; j < 4; ++j)
            #pragma unroll
            for (int r = 0; r < 4; ++r) c[i][j][r] = 0.f;

    const char* srcp[8];
    uint32_t dsto[8];
    #pragma unroll
    for (int q = 0; q < 8; ++q) {
        const int ch = tid + q*256;
        const int tile = ch >> 9, row = (ch & 511) >> 2, seg = (ch & 3) * 16;
        const __nv_bfloat16* base = (tile==0)?Ah:(tile==1)?Al:(tile==2)?Wh:Wl;
        const int rowbase = (tile < 2) ? bm : bn;
        srcp[q] = (const char*)(base + (size_t)(rowbase + row)*E_) + seg;
        dsto[q] = (uint32_t)(tile*TILE_BYTES + row*TSTRIDE + seg);
    }

    #define ISSUE(s) do { \
        const uint32_t dstbuf = sbase + (uint32_t)((s)&1)*BUF_BYTES; \
        const size_t soff = (size_t)(s)*64; \
        _Pragma("unroll") \
        for (int q = 0; q < 8; ++q) CPA16(dstbuf + dsto[q], srcp[q] + soff); \
        CPA_COMMIT(); \
    } while(0)

    ISSUE(0); ISSUE(1);
    const int lrow15 = lane & 15;
    const uint32_t kseg = (lane >> 4) * 16;

    for (int s = 0; s < 32; ++s) {
        if (s < 31) CPA_WAIT1(); else CPA_WAIT0();
        __syncthreads();
        const uint32_t buf = sbase + (uint32_t)(s & 1)*BUF_BYTES;
        #pragma unroll
        for (int k16 = 0; k16 < 2; ++k16) {
            const uint32_t koff = k16*32 + kseg;
            uint32_t bh[4][2], bl[4][2];
            #pragma unroll
            for (int p = 0; p < 2; ++p) {
                const int n = warp_n*32 + p*16 + lrow15;
                uint32_t r[4];
                ldsm4(r, buf + 2*TILE_BYTES + n*TSTRIDE + koff);
                bh[2*p][0]=r[0]; bh[2*p][1]=r[2]; bh[2*p+1][0]=r[1]; bh[2*p+1][1]=r[3];
                ldsm4(r, buf + 3*TILE_BYTES + n*TSTRIDE + koff);
                bl[2*p][0]=r[0]; bl[2*p][1]=r[2]; bl[2*p+1][0]=r[1]; bl[2*p+1][1]=r[3];
            }
            #pragma unroll
            for (int mf = 0; mf < 4; ++mf) {
                const int m = warp_m*64 + mf*16 + lrow15;
                uint32_t ah[4], al[4];
                ldsm4(ah, buf + 0*TILE_BYTES + m*TSTRIDE + koff);
                ldsm4(al, buf + 1*TILE_BYTES + m*TSTRIDE + koff);
                #pragma unroll
                for (int nf = 0; nf < 4; ++nf) {
                    mma16816(c[mf][nf], ah, bh[nf]);
                    mma16816(c[mf][nf], ah, bl[nf]);
                    mma16816(c[mf][nf], al, bh[nf]);
                }
            }
        }
        __syncthreads();
        if (s + 2 < 32) ISSUE(s + 2);
    }

    // ---------------- epilogue ----------------
    const int tq = lane >> 2, tr = lane & 3;
    #pragma unroll
    for (int mf = 0; mf < 4; ++mf) {
        #pragma unroll
        for (int nf = 0; nf < 4; ++nf) {
            #pragma unroll
            for (int half = 0; half < 2; ++half) {
                const int m = bm + warp_m*64 + mf*16 + tq + half*8;
                const int n0 = bn + warp_n*32 + nf*8 + tr*2;
                float v0 = c[mf][nf][half*2 + 0] + bias[n0];
                float v1 = c[mf][nf][half*2 + 1] + bias[n0 + 1];
                const int bb = m >> 11, t = m & 2047;
                if (z <= 2) {
                    const int h = n0 >> 6, hd = n0 & 63;
                    float* dst = ((z==0) ? g_Q : (z==1) ? g_K : g_V)
                                 + (((size_t)(bb*H_ + h) * T_ + t) * HD_) + hd;
                    if (z <= 1) {
                        const float4 cs = g_rope[(size_t)t*32 + (hd >> 1)];
                        *(float2*)dst = make_float2(v0*cs.x - v1*cs.y, v1*cs.z + v0*cs.w);
                    } else {
                        *(float2*)dst = make_float2(v0, v1);
                    }
                } else if (z == 3) {
                    g_G[(size_t)m*E_ + n0]     = v0 / (1.f + __expf(-v0));
                    g_G[(size_t)m*E_ + n0 + 1] = v1 / (1.f + __expf(-v1));
                } else {
                    *(float2*)(Cout + (size_t)m*E_ + n0) = make_float2(v0, v1);
                }
            }
        }
    }
    #undef ISSUE
}

// ---------------- Pass 1: backward chunk-state scan ----------------
__global__ __launch_bounds__(256) void ret_state_kernel()
{
    __shared__ float Ks[64][64];
    __shared__ float Vs[64][16];
    __shared__ float dec_s[65];

    const int eb = blockIdx.x, bh = blockIdx.y, h = bh & 15;
    const int tid = threadIdx.x;
    const int d = tid >> 2, eq = (tid & 3) * 4, e0 = eb * 16;

    if (tid < 65) dec_s[tid] = g_decay[h*T_ + tid];

    const float* Kg = g_K + (size_t)bh * T_ * HD_;
    const float* Vg = g_V + (size_t)bh * T_ * HD_;
    float* Rg = g_R + (size_t)bh * NT_ * (HD_*HD_);
    const int lrow = tid >> 2, lseg = (tid & 3) * 16;

    float R0=0.f, R1=0.f, R2=0.f, R3=0.f;
    *(float4*)&Rg[((NT_-1)*64 + d)*64 + e0 + eq] = make_float4(0.f,0.f,0.f,0.f);
    __syncthreads();
    const float gL = dec_s[64];

    for (int cc = NT_-1; cc >= 1; --cc) {
        const int j0 = cc * 64;
        {
            const float4* ks = (const float4*)(Kg + (size_t)(j0+lrow)*64 + lseg);
            float4* kd = (float4*)(&Ks[lrow][lseg]);
            #pragma unroll
            for (int q = 0; q < 4; ++q) kd[q] = ks[q];
            *(float4*)&Vs[lrow][(tid&3)*4] = *(const float4*)(Vg + (size_t)(j0+lrow)*64 + e0 + (tid&3)*4);
        }
        __syncthreads();
        float a0=0.f,a1=0.f,a2=0.f,a3=0.f;
        #pragma unroll 8
        for (int i = 0; i < 64; ++i) {
            const float kw = Ks[i][d] * dec_s[i];
            const float4 v = *(const float4*)&Vs[i][eq];
            a0 = fmaf(kw, v.x, a0); a1 = fmaf(kw, v.y, a1);
            a2 = fmaf(kw, v.z, a2); a3 = fmaf(kw, v.w, a3);
        }
        R0 = a0 + gL*R0; R1 = a1 + gL*R1; R2 = a2 + gL*R2; R3 = a3 + gL*R3;
        *(float4*)&Rg[((cc-1)*64 + d)*64 + e0 + eq] = make_float4(R0,R1,R2,R3);
        __syncthreads();
    }
}

// ---------------- Pass 2: intra-chunk + cross-chunk ----------------
__global__ __launch_bounds__(256) void ret_attn_kernel()
{
    __shared__ float Qs[64][64];
    __shared__ float KS[64][64];
    __shared__ float Vs[64][64];

    const int bh = blockIdx.y, b = bh >> 4, h = bh & 15;
    const int cI = blockIdx.x, q0 = cI * 64;

    const float* Qg = g_Q + (size_t)bh * T_ * HD_;
    const float* Kg = g_K + (size_t)bh * T_ * HD_;
    const float* Vg = g_V + (size_t)bh * T_ * HD_;
    const float* dec = g_decay + h * T_;
    const float* Rg = g_R + ((size_t)bh * NT_ + cI) * (HD_*HD_);

    const int tid = threadIdx.x;
    const int tx = tid & 15, ty = tid >> 4;
    const int lrow = tid >> 2, lseg = (tid & 3) * 16;

    {
        const float4* qsrc = (const float4*)(Qg + (size_t)(q0+lrow)*64 + lseg);
        float4* qdst = (float4*)(&Qs[lrow][lseg]);
        #pragma unroll
        for (int q = 0; q < 4; ++q) qdst[q] = qsrc[q];
        float4 k4[4];
        const float4* ks = (const float4*)(Kg + (size_t)(q0+lrow)*64 + lseg);
        #pragma unroll
        for (int q = 0; q < 4; ++q) k4[q] = ks[q];
        #pragma unroll
        for (int q = 0; q < 4; ++q) {
            KS[lseg+q*4+0][lrow] = k4[q].x; KS[lseg+q*4+1][lrow] = k4[q].y;
            KS[lseg+q*4+2][lrow] = k4[q].z; KS[lseg+q*4+3][lrow] = k4[q].w;
        }
        const float4* vs = (const float4*)(Vg + (size_t)(q0+lrow)*64 + lseg);
        float4* vd = (float4*)(&Vs[lrow][lseg]);
        #pragma unroll
        for (int q = 0; q < 4; ++q) vd[q] = vs[q];
    }
    __syncthreads();

    const float invsc = 0.125f;
    float s[4][4];
    #pragma unroll
    for (int i = 0; i < 4; ++i)
        #pragma unroll
        for (int j = 0; j < 4; ++j) s[i][j] = 0.f;

    #pragma unroll 8
    for (int k = 0; k < 64; ++k) {
        float4 kv = *(const float4*)(&KS[k][tx*4]);
        float qv[4];
        #pragma unroll
        for (int i = 0; i < 4; ++i) qv[i] = Qs[ty*4+i][k];
        #pragma unroll
        for (int i = 0; i < 4; ++i) {
            s[i][0] = fmaf(qv[i], kv.x, s[i][0]); s[i][1] = fmaf(qv[i], kv.y, s[i][1]);
            s[i][2] = fmaf(qv[i], kv.z, s[i][2]); s[i][3] = fmaf(qv[i], kv.w, s[i][3]);
        }
    }
    #pragma unroll
    for (int i = 0; i < 4; ++i) {
        const int ii = ty*4 + i;
        #pragma unroll
        for (int j = 0; j < 4; ++j) {
            const int jj = tx*4 + j;
            s[i][j] = (jj >= ii) ? s[i][j] * invsc * dec[jj-ii] : 0.f;
        }
    }
    __syncthreads();
    #pragma unroll
    for (int i = 0; i < 4; ++i)
        *(float4*)(&KS[ty*4+i][tx*4]) = make_float4(s[i][0], s[i][1], s[i][2], s[i][3]);
    __syncthreads();

    float o[4][4];
    #pragma unroll
    for (int i = 0; i < 4; ++i)
        #pragma unroll
        for (int j = 0; j < 4; ++j) o[i][j] = 0.f;

    #pragma unroll 8
    for (int k = 0; k < 64; ++k) {
        float4 vv = *(const float4*)(&Vs[k][tx*4]);
        float sv[4];
        #pragma unroll
        for (int i = 0; i < 4; ++i) sv[i] = KS[ty*4+i][k];
        #pragma unroll
        for (int i = 0; i < 4; ++i) {
            o[i][0] = fmaf(sv[i], vv.x, o[i][0]); o[i][1] = fmaf(sv[i], vv.y, o[i][1]);
            o[i][2] = fmaf(sv[i], vv.z, o[i][2]); o[i][3] = fmaf(sv[i], vv.w, o[i][3]);
        }
    }

    float cr[4][4];
    #pragma unroll
    for (int i = 0; i < 4; ++i)
        #pragma unroll
        for (int j = 0; j < 4; ++j) cr[i][j] = 0.f;
    #pragma unroll 4
    for (int d = 0; d < 64; ++d) {
        const float4 rv = __ldg((const float4*)&Rg[d*64 + tx*4]);
        float qd[4];
        #pragma unroll
        for (int i = 0; i < 4; ++i) qd[i] = Qs[ty*4+i][d];
        #pragma unroll
        for (int i = 0; i < 4; ++i) {
            cr[i][0] = fmaf(qd[i], rv.x, cr[i][0]); cr[i][1] = fmaf(qd[i], rv.y, cr[i][1]);
            cr[i][2] = fmaf(qd[i], rv.z, cr[i][2]); cr[i][3] = fmaf(qd[i], rv.w, cr[i][3]);
        }
    }
    #pragma unroll
    for (int i = 0; i < 4; ++i) {
        const int ii = ty*4 + i;
        const float coef = invsc * dec[64 - ii];
        #pragma unroll
        for (int j = 0; j < 4; ++j) o[i][j] = fmaf(coef, cr[i][j], o[i][j]);
    }
    #pragma unroll
    for (int i = 0; i < 4; ++i) {
        const int t = q0 + ty*4 + i;
        float* dst = g_O + ((size_t)(b*T_ + t)) * E_ + h*64 + tx*4;
        *(float4*)dst = make_float4(o[i][0], o[i][1], o[i][2], o[i][3]);
    }
}

// ---------------- GroupNorm stats (8 slices per bh, atomic partials) ----------------
__global__ __launch_bounds__(256) void gn_stats_kernel()
{
    const int bh = blockIdx.x >> 3, slice = blockIdx.x & 7;
    const int b = bh >> 4, h = bh & 15;
    const size_t base = (size_t)b * T_ * E_ + h * 64;
    const int t0 = slice * (T_/8);

    float sum = 0.f, sumsq = 0.f;
    for (int i = threadIdx.x; i < (T_/8)*64; i += 256) {
        const int t = t0 + (i >> 6), hd = i & 63;
        const float v = g_O[base + (size_t)t * E_ + hd];
        sum += v; sumsq = fmaf(v, v, sumsq);
    }
    __shared__ float ssum[256], ssq[256];
    ssum[threadIdx.x] = sum; ssq[threadIdx.x] = sumsq;
    __syncthreads();
    for (int off = 128; off > 0; off >>= 1) {
        if (threadIdx.x < off) { ssum[threadIdx.x] += ssum[threadIdx.x+off]; ssq[threadIdx.x] += ssq[threadIdx.x+off]; }
        __syncthreads();
    }
    if (threadIdx.x == 0) {
        atomicAdd(&g_stat[bh].x, ssum[0]);
        atomicAdd(&g_stat[bh].y, ssq[0]);
    }
}

// ---------------- GroupNorm apply + gate -> bf16 split ----------------
__global__ __launch_bounds__(256) void gn_apply_kernel(
    const float* __restrict__ gn_w, const float* __restrict__ gn_b)
{
    const int i4 = blockIdx.x*256 + threadIdx.x;      // float4 index, 1M total
    const size_t i = (size_t)i4 * 4;
    const int e0 = (int)(i & (E_-1));
    const int bt = (int)(i >> 10);
    const int bh = (bt >> 11) * H_ + (e0 >> 6);

    const float2 st = g_stat[bh];
    const float N = (float)(T_ * HD_);
    const float mu = st.x / N;
    const float rs = rsqrtf(st.y / N - mu*mu + 1e-5f);

    const float4 o = *(const float4*)(g_O + i);
    const float4 g = *(const float4*)(g_G + i);
    const float4 w = *(const float4*)(gn_w + e0);
    const float4 bb = *(const float4*)(gn_b + e0);

    float out[4];
    out[0] = ((o.x - mu) * rs * w.x + bb.x) * g.x;
    out[1] = ((o.y - mu) * rs * w.y + bb.y) * g.y;
    out[2] = ((o.z - mu) * rs * w.z + bb.z) * g.z;
    out[3] = ((o.w - mu) * rs * w.w + bb.w) * g.w;

    __nv_bfloat16 hi[4], lo[4];
    #pragma unroll
    for (int q = 0; q < 4; ++q) {
        hi[q] = __float2bfloat16(out[q]);
        lo[q] = __float2bfloat16(out[q] - __bfloat162float(hi[q]));
    }
    *(uint2*)(g_Ah + i) = *(uint2*)hi;
    *(uint2*)(g_Al + i) = *(uint2*)lo;
}

// ---------------- launch ----------------
extern "C" void kernel_launch(void* const* d_in, const int* in_sizes, int n_in,
                              void* d_out, int out_size)
{
    const float* x    = (const float*)d_in[0];
    const float* Wq   = (const float*)d_in[1];
    const float* bq   = (const float*)d_in[2];
    const float* Wk   = (const float*)d_in[3];
    const float* bk   = (const float*)d_in[4];
    const float* Wv   = (const float*)d_in[5];
    const float* bv   = (const float*)d_in[6];
    const float* Wg   = (const float*)d_in[7];
    const float* bg   = (const float*)d_in[8];
    const float* Wo   = (const float*)d_in[9];
    const float* bo   = (const float*)d_in[10];
    const float* gn_w = (const float*)d_in[11];
    const float* gn_b = (const float*)d_in[12];

    __nv_bfloat16 *Ah, *Al;
    cudaGetSymbolAddress((void**)&Ah, g_Ah);
    cudaGetSymbolAddress((void**)&Al, g_Al);

    cudaFuncSetAttribute(tc_gemm, cudaFuncAttributeMaxDynamicSharedMemorySize, DYN_SMEM);

    decay_kernel<<<(H_*T_ + 255)/256, 256>>>();
    rope_table_kernel<<<(T_*32 + 255)/256, 256>>>();

    const int ntot = M_*E_ + 5*E_*E_;
    split_all_kernel<<<(ntot + 255)/256, 256>>>(x, Wq, Wk, Wv, Wg, Wo);

    tc_gemm<<<dim3(E_/128, M_/128, 4), 256, DYN_SMEM>>>(Ah, Al, bq, bk, bv, bg, nullptr, -1);

    ret_state_kernel<<<dim3(4, B_*H_), 256>>>();
    ret_attn_kernel<<<dim3(NT_, B_*H_), 256>>>();

    gn_stats_kernel<<<B_*H_*8, 256>>>();
    gn_apply_kernel<<<(M_*E_/4 + 255)/256, 256>>>(gn_w, gn_b);

    tc_gemm<<<dim3(E_/128, M_/128, 1), 256, DYN_SMEM>>>(Ah, Al, bo, nullptr, nullptr, nullptr,
                                                        (float*)d_out, 4);
}

// round 9
// speedup vs baseline: 3.6749x; 1.0131x over previous
#include <cuda_runtime.h>
#include <cuda_bf16.h>
#include <math.h>
#include <stdint.h>

#define B_  2
#define T_  2048
#define E_  1024
#define H_  16
#define HD_ 64
#define M_  (B_*T_)
#define NT_ (T_/64)

#define TSTRIDE 80
#define TILE_BYTES (128*TSTRIDE)
#define BUF_BYTES (4*TILE_BYTES)     // 40960
#define NSTAGE 2
#define DYN_SMEM (NSTAGE*BUF_BYTES)  // 81920 -> 2 CTAs/SM

// ---------------- scratch ----------------
__device__ float g_Q[B_*H_*T_*HD_];
__device__ float g_K[B_*H_*T_*HD_];
__device__ float g_V[B_*H_*T_*HD_];
__device__ float g_G[B_*T_*E_];
__device__ float g_O[B_*T_*E_];
__device__ float g_decay[H_*T_];
__device__ float g_R[B_*H_*NT_*HD_*HD_];
__device__ float4 g_rope[T_*32];
__device__ float2 g_stat[B_*H_];
__device__ __nv_bfloat16 g_Ah[M_*E_], g_Al[M_*E_];
__device__ __nv_bfloat16 g_Wh[5*E_*E_], g_Wl[5*E_*E_];

// ---------------- helpers ----------------
__device__ __forceinline__ uint32_t smem_u32(const void* p){
    uint32_t a; asm("{ .reg .u64 t; cvta.to.shared.u64 t, %1; cvt.u32.u64 %0, t; }":"=r"(a):"l"(p)); return a;
}
__device__ __forceinline__ void ldsm4(uint32_t r[4], uint32_t a){
    asm volatile("ldmatrix.sync.aligned.m8n8.x4.shared.b16 {%0,%1,%2,%3}, [%4];"
        :"=r"(r[0]),"=r"(r[1]),"=r"(r[2]),"=r"(r[3]):"r"(a));
}
__device__ __forceinline__ void mma16816(float c[4], const uint32_t a[4], const uint32_t b[2]){
    asm volatile("mma.sync.aligned.m16n8k16.row.col.f32.bf16.bf16.f32 "
        "{%0,%1,%2,%3}, {%4,%5,%6,%7}, {%8,%9}, {%0,%1,%2,%3};"
        : "+f"(c[0]),"+f"(c[1]),"+f"(c[2]),"+f"(c[3])
        : "r"(a[0]),"r"(a[1]),"r"(a[2]),"r"(a[3]),"r"(b[0]),"r"(b[1]));
}
#define CPA16(dst, src)  asm volatile("cp.async.cg.shared.global [%0], [%1], 16;"::"r"(dst),"l"(src))
#define CPA_COMMIT()     asm volatile("cp.async.commit_group;":::"memory")
#define CPA_WAIT1()      asm volatile("cp.async.wait_group 1;":::"memory")
#define CPA_WAIT0()      asm volatile("cp.async.wait_group 0;":::"memory")

// ---------------- prep ----------------
__global__ void split_all_kernel(const float* __restrict__ x,
    const float* __restrict__ Wq, const float* __restrict__ Wk,
    const float* __restrict__ Wv, const float* __restrict__ Wg,
    const float* __restrict__ Wo)
{
    const int i = blockIdx.x*256 + threadIdx.x;
    const int NX = M_*E_;
    float v; __nv_bfloat16 *hi, *lo;
    if (i < NX) {
        v = x[i]; hi = g_Ah + i; lo = g_Al + i;
    } else {
        const int j = i - NX;
        const int w = j >> 20, off = j & ((1<<20)-1);
        const float* src = (w==0)?Wq:(w==1)?Wk:(w==2)?Wv:(w==3)?Wg:Wo;
        v = src[off]; hi = g_Wh + j; lo = g_Wl + j;
    }
    const __nv_bfloat16 h = __float2bfloat16(v);
    *hi = h; *lo = __float2bfloat16(v - __bfloat162float(h));
}

// decay table + rope table + stat zero, one launch (64K threads)
__global__ void tables_kernel()
{
    const int idx = blockIdx.x*256 + threadIdx.x;
    if (idx < B_*H_) g_stat[idx] = make_float2(0.f, 0.f);
    if (idx < H_*T_) {
        const int h = idx >> 11, d = idx & 2047;
        const double gamma = 1.0 - exp2(-(double)(5 + h));
        g_decay[idx] = (float)pow(gamma, (double)d);
    }
    if (idx < T_*32) {
        const int t = idx >> 5, p = idx & 31;
        float inv0 = (float)pow(10000.0, -(double)((2*p)   & 31) / 32.0);
        float inv1 = (float)pow(10000.0, -(double)((2*p+1) & 31) / 32.0);
        float s0,c0,s1,c1;
        sincosf((float)t * inv0, &s0, &c0);
        sincosf((float)t * inv1, &s1, &c1);
        g_rope[idx] = make_float4(c0, s0, c1, s1);
    }
}

// ---------------- HMMA GEMM 128x128 tile, bf16 3-term split, 2 CTAs/SM ----------------
__global__ __launch_bounds__(256, 2) void tc_gemm(
    const __nv_bfloat16* __restrict__ Ah, const __nv_bfloat16* __restrict__ Al,
    const float* __restrict__ b0, const float* __restrict__ b1,
    const float* __restrict__ b2, const float* __restrict__ b3,
    float* __restrict__ Cout, int single_mode)
{
    extern __shared__ __align__(16) char smem[];
    const int z = (single_mode >= 0) ? 4 : blockIdx.z;
    const float* bias = (z==1) ? b1 : (z==2) ? b2 : (z==3) ? b3 : b0;
    const __nv_bfloat16* Wh = g_Wh + (size_t)z * (E_*E_);
    const __nv_bfloat16* Wl = g_Wl + (size_t)z * (E_*E_);
    const int bm = blockIdx.y * 128, bn = blockIdx.x * 128;
    const int tid = threadIdx.x, wid = tid >> 5, lane = tid & 31;
    const int warp_m = wid >> 2, warp_n = wid & 3;
    const uint32_t sbase = smem_u32(smem);

    float c[4][4][4];
    #pragma unroll
    for (int i = 0; i < 4; ++i)
        #pragma unroll
        for (int j = 0; j < 4; ++j)
            #pragma unroll
            for (int r = 0; r < 4; ++r) c[i][j][r] = 0.f;

    const char* srcp[8];
    uint32_t dsto[8];
    #pragma unroll
    for (int q = 0; q < 8; ++q) {
        const int ch = tid + q*256;
        const int tile = ch >> 9, row = (ch & 511) >> 2, seg = (ch & 3) * 16;
        const __nv_bfloat16* base = (tile==0)?Ah:(tile==1)?Al:(tile==2)?Wh:Wl;
        const int rowbase = (tile < 2) ? bm : bn;
        srcp[q] = (const char*)(base + (size_t)(rowbase + row)*E_) + seg;
        dsto[q] = (uint32_t)(tile*TILE_BYTES + row*TSTRIDE + seg);
    }

    #define ISSUE(s) do { \
        const uint32_t dstbuf = sbase + (uint32_t)((s)&1)*BUF_BYTES; \
        const size_t soff = (size_t)(s)*64; \
        _Pragma("unroll") \
        for (int q = 0; q < 8; ++q) CPA16(dstbuf + dsto[q], srcp[q] + soff); \
        CPA_COMMIT(); \
    } while(0)

    ISSUE(0); ISSUE(1);
    const int lrow15 = lane & 15;
    const uint32_t kseg = (lane >> 4) * 16;

    // hoisted ldsm row-address components (buffer-relative)
    uint32_t a_off[4], b_off[2];
    #pragma unroll
    for (int mf = 0; mf < 4; ++mf)
        a_off[mf] = (uint32_t)((warp_m*64 + mf*16 + lrow15) * TSTRIDE) + kseg;
    #pragma unroll
    for (int p = 0; p < 2; ++p)
        b_off[p] = (uint32_t)((warp_n*32 + p*16 + lrow15) * TSTRIDE) + kseg + 2*TILE_BYTES;

    for (int s = 0; s < 32; ++s) {
        if (s < 31) CPA_WAIT1(); else CPA_WAIT0();
        __syncthreads();
        const uint32_t buf = sbase + (uint32_t)(s & 1)*BUF_BYTES;

        // prefetch ALL B fragments for both k16 halves (8 ldsm, high MLP)
        uint32_t bh[2][4][2], bl[2][4][2];
        #pragma unroll
        for (int k16 = 0; k16 < 2; ++k16) {
            const uint32_t koff = buf + k16*32;
            #pragma unroll
            for (int p = 0; p < 2; ++p) {
                uint32_t r[4];
                ldsm4(r, koff + b_off[p]);
                bh[k16][2*p][0]=r[0]; bh[k16][2*p][1]=r[2];
                bh[k16][2*p+1][0]=r[1]; bh[k16][2*p+1][1]=r[3];
                ldsm4(r, koff + b_off[p] + TILE_BYTES);
                bl[k16][2*p][0]=r[0]; bl[k16][2*p][1]=r[2];
                bl[k16][2*p+1][0]=r[1]; bl[k16][2*p+1][1]=r[3];
            }
        }
        #pragma unroll
        for (int k16 = 0; k16 < 2; ++k16) {
            const uint32_t koff = buf + k16*32;
            #pragma unroll
            for (int mf = 0; mf < 4; ++mf) {
                uint32_t ah[4], al[4];
                ldsm4(ah, koff + a_off[mf]);
                ldsm4(al, koff + a_off[mf] + TILE_BYTES);
                #pragma unroll
                for (int nf = 0; nf < 4; ++nf) {
                    mma16816(c[mf][nf], ah, bh[k16][nf]);
                    mma16816(c[mf][nf], ah, bl[k16][nf]);
                    mma16816(c[mf][nf], al, bh[k16][nf]);
                }
            }
        }
        __syncthreads();
        if (s + 2 < 32) ISSUE(s + 2);
    }

    // ---------------- epilogue ----------------
    const int tq = lane >> 2, tr = lane & 3;
    #pragma unroll
    for (int mf = 0; mf < 4; ++mf) {
        #pragma unroll
        for (int nf = 0; nf < 4; ++nf) {
            #pragma unroll
            for (int half = 0; half < 2; ++half) {
                const int m = bm + warp_m*64 + mf*16 + tq + half*8;
                const int n0 = bn + warp_n*32 + nf*8 + tr*2;
                float v0 = c[mf][nf][half*2 + 0] + bias[n0];
                float v1 = c[mf][nf][half*2 + 1] + bias[n0 + 1];
                const int bb = m >> 11, t = m & 2047;
                if (z <= 2) {
                    const int h = n0 >> 6, hd = n0 & 63;
                    float* dst = ((z==0) ? g_Q : (z==1) ? g_K : g_V)
                                 + (((size_t)(bb*H_ + h) * T_ + t) * HD_) + hd;
                    if (z <= 1) {
                        const float4 cs = g_rope[(size_t)t*32 + (hd >> 1)];
                        *(float2*)dst = make_float2(v0*cs.x - v1*cs.y, v1*cs.z + v0*cs.w);
                    } else {
                        *(float2*)dst = make_float2(v0, v1);
                    }
                } else if (z == 3) {
                    g_G[(size_t)m*E_ + n0]     = v0 / (1.f + __expf(-v0));
                    g_G[(size_t)m*E_ + n0 + 1] = v1 / (1.f + __expf(-v1));
                } else {
                    *(float2*)(Cout + (size_t)m*E_ + n0) = make_float2(v0, v1);
                }
            }
        }
    }
    #undef ISSUE
}

// ---------------- Pass 1: backward chunk-state scan ----------------
__global__ __launch_bounds__(256) void ret_state_kernel()
{
    __shared__ float Ks[64][64];
    __shared__ float Vs[64][16];
    __shared__ float dec_s[65];

    const int eb = blockIdx.x, bh = blockIdx.y, h = bh & 15;
    const int tid = threadIdx.x;
    const int d = tid >> 2, eq = (tid & 3) * 4, e0 = eb * 16;

    if (tid < 65) dec_s[tid] = g_decay[h*T_ + tid];

    const float* Kg = g_K + (size_t)bh * T_ * HD_;
    const float* Vg = g_V + (size_t)bh * T_ * HD_;
    float* Rg = g_R + (size_t)bh * NT_ * (HD_*HD_);
    const int lrow = tid >> 2, lseg = (tid & 3) * 16;

    float R0=0.f, R1=0.f, R2=0.f, R3=0.f;
    *(float4*)&Rg[((NT_-1)*64 + d)*64 + e0 + eq] = make_float4(0.f,0.f,0.f,0.f);
    __syncthreads();
    const float gL = dec_s[64];

    for (int cc = NT_-1; cc >= 1; --cc) {
        const int j0 = cc * 64;
        {
            const float4* ks = (const float4*)(Kg + (size_t)(j0+lrow)*64 + lseg);
            float4* kd = (float4*)(&Ks[lrow][lseg]);
            #pragma unroll
            for (int q = 0; q < 4; ++q) kd[q] = ks[q];
            *(float4*)&Vs[lrow][(tid&3)*4] = *(const float4*)(Vg + (size_t)(j0+lrow)*64 + e0 + (tid&3)*4);
        }
        __syncthreads();
        float a0=0.f,a1=0.f,a2=0.f,a3=0.f;
        #pragma unroll 8
        for (int i = 0; i < 64; ++i) {
            const float kw = Ks[i][d] * dec_s[i];
            const float4 v = *(const float4*)&Vs[i][eq];
            a0 = fmaf(kw, v.x, a0); a1 = fmaf(kw, v.y, a1);
            a2 = fmaf(kw, v.z, a2); a3 = fmaf(kw, v.w, a3);
        }
        R0 = a0 + gL*R0; R1 = a1 + gL*R1; R2 = a2 + gL*R2; R3 = a3 + gL*R3;
        *(float4*)&Rg[((cc-1)*64 + d)*64 + e0 + eq] = make_float4(R0,R1,R2,R3);
        __syncthreads();
    }
}

// ---------------- Pass 2: intra-chunk + cross-chunk ----------------
__global__ __launch_bounds__(256) void ret_attn_kernel()
{
    __shared__ float Qs[64][64];
    __shared__ float KS[64][64];
    __shared__ float Vs[64][64];

    const int bh = blockIdx.y, b = bh >> 4, h = bh & 15;
    const int cI = blockIdx.x, q0 = cI * 64;

    const float* Qg = g_Q + (size_t)bh * T_ * HD_;
    const float* Kg = g_K + (size_t)bh * T_ * HD_;
    const float* Vg = g_V + (size_t)bh * T_ * HD_;
    const float* dec = g_decay + h * T_;
    const float* Rg = g_R + ((size_t)bh * NT_ + cI) * (HD_*HD_);

    const int tid = threadIdx.x;
    const int tx = tid & 15, ty = tid >> 4;
    const int lrow = tid >> 2, lseg = (tid & 3) * 16;

    {
        const float4* qsrc = (const float4*)(Qg + (size_t)(q0+lrow)*64 + lseg);
        float4* qdst = (float4*)(&Qs[lrow][lseg]);
        #pragma unroll
        for (int q = 0; q < 4; ++q) qdst[q] = qsrc[q];
        float4 k4[4];
        const float4* ks = (const float4*)(Kg + (size_t)(q0+lrow)*64 + lseg);
        #pragma unroll
        for (int q = 0; q < 4; ++q) k4[q] = ks[q];
        #pragma unroll
        for (int q = 0; q < 4; ++q) {
            KS[lseg+q*4+0][lrow] = k4[q].x; KS[lseg+q*4+1][lrow] = k4[q].y;
            KS[lseg+q*4+2][lrow] = k4[q].z; KS[lseg+q*4+3][lrow] = k4[q].w;
        }
        const float4* vs = (const float4*)(Vg + (size_t)(q0+lrow)*64 + lseg);
        float4* vd = (float4*)(&Vs[lrow][lseg]);
        #pragma unroll
        for (int q = 0; q < 4; ++q) vd[q] = vs[q];
    }
    __syncthreads();

    const float invsc = 0.125f;
    float s[4][4];
    #pragma unroll
    for (int i = 0; i < 4; ++i)
        #pragma unroll
        for (int j = 0; j < 4; ++j) s[i][j] = 0.f;

    #pragma unroll 8
    for (int k = 0; k < 64; ++k) {
        float4 kv = *(const float4*)(&KS[k][tx*4]);
        float qv[4];
        #pragma unroll
        for (int i = 0; i < 4; ++i) qv[i] = Qs[ty*4+i][k];
        #pragma unroll
        for (int i = 0; i < 4; ++i) {
            s[i][0] = fmaf(qv[i], kv.x, s[i][0]); s[i][1] = fmaf(qv[i], kv.y, s[i][1]);
            s[i][2] = fmaf(qv[i], kv.z, s[i][2]); s[i][3] = fmaf(qv[i], kv.w, s[i][3]);
        }
    }
    #pragma unroll
    for (int i = 0; i < 4; ++i) {
        const int ii = ty*4 + i;
        #pragma unroll
        for (int j = 0; j < 4; ++j) {
            const int jj = tx*4 + j;
            s[i][j] = (jj >= ii) ? s[i][j] * invsc * dec[jj-ii] : 0.f;
        }
    }
    __syncthreads();
    #pragma unroll
    for (int i = 0; i < 4; ++i)
        *(float4*)(&KS[ty*4+i][tx*4]) = make_float4(s[i][0], s[i][1], s[i][2], s[i][3]);
    __syncthreads();

    float o[4][4];
    #pragma unroll
    for (int i = 0; i < 4; ++i)
        #pragma unroll
        for (int j = 0; j < 4; ++j) o[i][j] = 0.f;

    #pragma unroll 8
    for (int k = 0; k < 64; ++k) {
        float4 vv = *(const float4*)(&Vs[k][tx*4]);
        float sv[4];
        #pragma unroll
        for (int i = 0; i < 4; ++i) sv[i] = KS[ty*4+i][k];
        #pragma unroll
        for (int i = 0; i < 4; ++i) {
            o[i][0] = fmaf(sv[i], vv.x, o[i][0]); o[i][1] = fmaf(sv[i], vv.y, o[i][1]);
            o[i][2] = fmaf(sv[i], vv.z, o[i][2]); o[i][3] = fmaf(sv[i], vv.w, o[i][3]);
        }
    }

    float cr[4][4];
    #pragma unroll
    for (int i = 0; i < 4; ++i)
        #pragma unroll
        for (int j = 0; j < 4; ++j) cr[i][j] = 0.f;
    #pragma unroll 4
    for (int d = 0; d < 64; ++d) {
        const float4 rv = __ldg((const float4*)&Rg[d*64 + tx*4]);
        float qd[4];
        #pragma unroll
        for (int i = 0; i < 4; ++i) qd[i] = Qs[ty*4+i][d];
        #pragma unroll
        for (int i = 0; i < 4; ++i) {
            cr[i][0] = fmaf(qd[i], rv.x, cr[i][0]); cr[i][1] = fmaf(qd[i], rv.y, cr[i][1]);
            cr[i][2] = fmaf(qd[i], rv.z, cr[i][2]); cr[i][3] = fmaf(qd[i], rv.w, cr[i][3]);
        }
    }
    #pragma unroll
    for (int i = 0; i < 4; ++i) {
        const int ii = ty*4 + i;
        const float coef = invsc * dec[64 - ii];
        #pragma unroll
        for (int j = 0; j < 4; ++j) o[i][j] = fmaf(coef, cr[i][j], o[i][j]);
    }
    #pragma unroll
    for (int i = 0; i < 4; ++i) {
        const int t = q0 + ty*4 + i;
        float* dst = g_O + ((size_t)(b*T_ + t)) * E_ + h*64 + tx*4;
        *(float4*)dst = make_float4(o[i][0], o[i][1], o[i][2], o[i][3]);
    }
}

// ---------------- GroupNorm stats ----------------
__global__ __launch_bounds__(256) void gn_stats_kernel()
{
    const int bh = blockIdx.x >> 3, slice = blockIdx.x & 7;
    const int b = bh >> 4, h = bh & 15;
    const size_t base = (size_t)b * T_ * E_ + h * 64;
    const int t0 = slice * (T_/8);

    float sum = 0.f, sumsq = 0.f;
    for (int i = threadIdx.x; i < (T_/8)*64; i += 256) {
        const int t = t0 + (i >> 6), hd = i & 63;
        const float v = g_O[base + (size_t)t * E_ + hd];
        sum += v; sumsq = fmaf(v, v, sumsq);
    }
    __shared__ float ssum[256], ssq[256];
    ssum[threadIdx.x] = sum; ssq[threadIdx.x] = sumsq;
    __syncthreads();
    for (int off = 128; off > 0; off >>= 1) {
        if (threadIdx.x < off) { ssum[threadIdx.x] += ssum[threadIdx.x+off]; ssq[threadIdx.x] += ssq[threadIdx.x+off]; }
        __syncthreads();
    }
    if (threadIdx.x == 0) {
        atomicAdd(&g_stat[bh].x, ssum[0]);
        atomicAdd(&g_stat[bh].y, ssq[0]);
    }
}

// ---------------- GroupNorm apply + gate -> bf16 split ----------------
__global__ __launch_bounds__(256) void gn_apply_kernel(
    const float* __restrict__ gn_w, const float* __restrict__ gn_b)
{
    const int i4 = blockIdx.x*256 + threadIdx.x;
    const size_t i = (size_t)i4 * 4;
    const int e0 = (int)(i & (E_-1));
    const int bt = (int)(i >> 10);
    const int bh = (bt >> 11) * H_ + (e0 >> 6);

    const float2 st = g_stat[bh];
    const float N = (float)(T_ * HD_);
    const float mu = st.x / N;
    const float rs = rsqrtf(st.y / N - mu*mu + 1e-5f);

    const float4 o = *(const float4*)(g_O + i);
    const float4 g = *(const float4*)(g_G + i);
    const float4 w = *(const float4*)(gn_w + e0);
    const float4 bb = *(const float4*)(gn_b + e0);

    float out[4];
    out[0] = ((o.x - mu) * rs * w.x + bb.x) * g.x;
    out[1] = ((o.y - mu) * rs * w.y + bb.y) * g.y;
    out[2] = ((o.z - mu) * rs * w.z + bb.z) * g.z;
    out[3] = ((o.w - mu) * rs * w.w + bb.w) * g.w;

    __nv_bfloat16 hi[4], lo[4];
    #pragma unroll
    for (int q = 0; q < 4; ++q) {
        hi[q] = __float2bfloat16(out[q]);
        lo[q] = __float2bfloat16(out[q] - __bfloat162float(hi[q]));
    }
    *(uint2*)(g_Ah + i) = *(uint2*)hi;
    *(uint2*)(g_Al + i) = *(uint2*)lo;
}

// ---------------- launch ----------------
extern "C" void kernel_launch(void* const* d_in, const int* in_sizes, int n_in,
                              void* d_out, int out_size)
{
    const float* x    = (const float*)d_in[0];
    const float* Wq   = (const float*)d_in[1];
    const float* bq   = (const float*)d_in[2];
    const float* Wk   = (const float*)d_in[3];
    const float* bk   = (const float*)d_in[4];
    const float* Wv   = (const float*)d_in[5];
    const float* bv   = (const float*)d_in[6];
    const float* Wg   = (const float*)d_in[7];
    const float* bg   = (const float*)d_in[8];
    const float* Wo   = (const float*)d_in[9];
    const float* bo   = (const float*)d_in[10];
    const float* gn_w = (const float*)d_in[11];
    const float* gn_b = (const float*)d_in[12];

    __nv_bfloat16 *Ah, *Al;
    cudaGetSymbolAddress((void**)&Ah, g_Ah);
    cudaGetSymbolAddress((void**)&Al, g_Al);

    cudaFuncSetAttribute(tc_gemm, cudaFuncAttributeMaxDynamicSharedMemorySize, DYN_SMEM);

    tables_kernel<<<(T_*32 + 255)/256, 256>>>();

    const int ntot = M_*E_ + 5*E_*E_;
    split_all_kernel<<<(ntot + 255)/256, 256>>>(x, Wq, Wk, Wv, Wg, Wo);

    tc_gemm<<<dim3(E_/128, M_/128, 4), 256, DYN_SMEM>>>(Ah, Al, bq, bk, bv, bg, nullptr, -1);

    ret_state_kernel<<<dim3(4, B_*H_), 256>>>();
    ret_attn_kernel<<<dim3(NT_, B_*H_), 256>>>();

    gn_stats_kernel<<<B_*H_*8, 256>>>();
    gn_apply_kernel<<<(M_*E_/4 + 255)/256, 256>>>(gn_w, gn_b);

    tc_gemm<<<dim3(E_/128, M_/128, 1), 256, DYN_SMEM>>>(Ah, Al, bo, nullptr, nullptr, nullptr,
                                                        (float*)d_out, 4);
}

// round 10
// speedup vs baseline: 3.9113x; 1.0643x over previous
#include <cuda_runtime.h>
#include <cuda_bf16.h>
#include <math.h>
#include <stdint.h>

#define B_  2
#define T_  2048
#define E_  1024
#define H_  16
#define HD_ 64
#define M_  (B_*T_)
#define NT_ (T_/64)

#define TSTRIDE 80
#define TILE_BYTES (128*TSTRIDE)
#define BUF_BYTES (4*TILE_BYTES)     // 40960
#define DYN_SMEM (2*BUF_BYTES)       // 81920 -> 2 CTAs/SM

// ---------------- scratch ----------------
__device__ float g_Q[B_*H_*T_*HD_];
__device__ float g_K[B_*H_*T_*HD_];
__device__ float g_V[B_*H_*T_*HD_];
__device__ float g_G[B_*T_*E_];
__device__ float g_O[B_*T_*E_];
__device__ float g_decay[H_*T_];
__device__ float g_R[B_*H_*NT_*HD_*HD_];
__device__ float g_U[B_*H_*NT_*HD_*HD_];
__device__ float4 g_rope[T_*32];
__device__ float2 g_stat[B_*H_];
__device__ __nv_bfloat16 g_Ah[M_*E_], g_Al[M_*E_];
__device__ __nv_bfloat16 g_Wh[5*E_*E_], g_Wl[5*E_*E_];

// ---------------- helpers ----------------
__device__ __forceinline__ uint32_t smem_u32(const void* p){
    uint32_t a; asm("{ .reg .u64 t; cvta.to.shared.u64 t, %1; cvt.u32.u64 %0, t; }":"=r"(a):"l"(p)); return a;
}
__device__ __forceinline__ void ldsm4(uint32_t r[4], uint32_t a){
    asm volatile("ldmatrix.sync.aligned.m8n8.x4.shared.b16 {%0,%1,%2,%3}, [%4];"
        :"=r"(r[0]),"=r"(r[1]),"=r"(r[2]),"=r"(r[3]):"r"(a));
}
__device__ __forceinline__ void mma16816(float c[4], const uint32_t a[4], const uint32_t b[2]){
    asm volatile("mma.sync.aligned.m16n8k16.row.col.f32.bf16.bf16.f32 "
        "{%0,%1,%2,%3}, {%4,%5,%6,%7}, {%8,%9}, {%0,%1,%2,%3};"
        : "+f"(c[0]),"+f"(c[1]),"+f"(c[2]),"+f"(c[3])
        : "r"(a[0]),"r"(a[1]),"r"(a[2]),"r"(a[3]),"r"(b[0]),"r"(b[1]));
}
#define CPA16(dst, src)  asm volatile("cp.async.cg.shared.global [%0], [%1], 16;"::"r"(dst),"l"(src))
#define CPA_COMMIT()     asm volatile("cp.async.commit_group;":::"memory")
#define CPA_WAIT1()      asm volatile("cp.async.wait_group 1;":::"memory")
#define CPA_WAIT0()      asm volatile("cp.async.wait_group 0;":::"memory")

// ---------------- prep ----------------
__global__ void split_all_kernel(const float* __restrict__ x,
    const float* __restrict__ Wq, const float* __restrict__ Wk,
    const float* __restrict__ Wv, const float* __restrict__ Wg,
    const float* __restrict__ Wo)
{
    const int i = blockIdx.x*256 + threadIdx.x;
    const int NX = M_*E_;
    float v; __nv_bfloat16 *hi, *lo;
    if (i < NX) {
        v = x[i]; hi = g_Ah + i; lo = g_Al + i;
    } else {
        const int j = i - NX;
        const int w = j >> 20, off = j & ((1<<20)-1);
        const float* src = (w==0)?Wq:(w==1)?Wk:(w==2)?Wv:(w==3)?Wg:Wo;
        v = src[off]; hi = g_Wh + j; lo = g_Wl + j;
    }
    const __nv_bfloat16 h = __float2bfloat16(v);
    *hi = h; *lo = __float2bfloat16(v - __bfloat162float(h));
}

__global__ void tables_kernel()
{
    const int idx = blockIdx.x*256 + threadIdx.x;
    if (idx < B_*H_) g_stat[idx] = make_float2(0.f, 0.f);
    if (idx < H_*T_) {
        const int h = idx >> 11, d = idx & 2047;
        const double gamma = 1.0 - exp2(-(double)(5 + h));
        g_decay[idx] = (float)pow(gamma, (double)d);
    }
    if (idx < T_*32) {
        const int t = idx >> 5, p = idx & 31;
        float inv0 = (float)pow(10000.0, -(double)((2*p)   & 31) / 32.0);
        float inv1 = (float)pow(10000.0, -(double)((2*p+1) & 31) / 32.0);
        float s0,c0,s1,c1;
        sincosf((float)t * inv0, &s0, &c0);
        sincosf((float)t * inv1, &s1, &c1);
        g_rope[idx] = make_float4(c0, s0, c1, s1);
    }
}

// ---------------- HMMA GEMM 128x128 tile, bf16 3-term split, 2 CTAs/SM ----------------
__global__ __launch_bounds__(256, 2) void tc_gemm(
    const __nv_bfloat16* __restrict__ Ah, const __nv_bfloat16* __restrict__ Al,
    const float* __restrict__ b0, const float* __restrict__ b1,
    const float* __restrict__ b2, const float* __restrict__ b3,
    float* __restrict__ Cout, int single_mode)
{
    extern __shared__ __align__(16) char smem[];
    const int z = (single_mode >= 0) ? 4 : blockIdx.z;
    const float* bias = (z==1) ? b1 : (z==2) ? b2 : (z==3) ? b3 : b0;
    const __nv_bfloat16* Wh = g_Wh + (size_t)z * (E_*E_);
    const __nv_bfloat16* Wl = g_Wl + (size_t)z * (E_*E_);
    const int bm = blockIdx.y * 128, bn = blockIdx.x * 128;
    const int tid = threadIdx.x, wid = tid >> 5, lane = tid & 31;
    const int warp_m = wid >> 2, warp_n = wid & 3;
    const uint32_t sbase = smem_u32(smem);

    float c[4][4][4];
    #pragma unroll
    for (int i = 0; i < 4; ++i)
        #pragma unroll
        for (int j = 0; j < 4; ++j)
            #pragma unroll
            for (int r = 0; r < 4; ++r) c[i][j][r] = 0.f;

    const char* srcp[8];
    uint32_t dsto[8];
    #pragma unroll
    for (int q = 0; q < 8; ++q) {
        const int ch = tid + q*256;
        const int tile = ch >> 9, row = (ch & 511) >> 2, seg = (ch & 3) * 16;
        const __nv_bfloat16* base = (tile==0)?Ah:(tile==1)?Al:(tile==2)?Wh:Wl;
        const int rowbase = (tile < 2) ? bm : bn;
        srcp[q] = (const char*)(base + (size_t)(rowbase + row)*E_) + seg;
        dsto[q] = (uint32_t)(tile*TILE_BYTES + row*TSTRIDE + seg);
    }

    #define ISSUE(s) do { \
        const uint32_t dstbuf = sbase + (uint32_t)((s)&1)*BUF_BYTES; \
        const size_t soff = (size_t)(s)*64; \
        _Pragma("unroll") \
        for (int q = 0; q < 8; ++q) CPA16(dstbuf + dsto[q], srcp[q] + soff); \
        CPA_COMMIT(); \
    } while(0)

    ISSUE(0); ISSUE(1);
    const int lrow15 = lane & 15;
    const uint32_t kseg = (lane >> 4) * 16;

    uint32_t a_off[4], b_off[2];
    #pragma unroll
    for (int mf = 0; mf < 4; ++mf)
        a_off[mf] = (uint32_t)((warp_m*64 + mf*16 + lrow15) * TSTRIDE) + kseg;
    #pragma unroll
    for (int p = 0; p < 2; ++p)
        b_off[p] = (uint32_t)((warp_n*32 + p*16 + lrow15) * TSTRIDE) + kseg + 2*TILE_BYTES;

    for (int s = 0; s < 32; ++s) {
        if (s < 31) CPA_WAIT1(); else CPA_WAIT0();
        __syncthreads();
        const uint32_t buf = sbase + (uint32_t)(s & 1)*BUF_BYTES;

        uint32_t bh[2][4][2], bl[2][4][2];
        #pragma unroll
        for (int k16 = 0; k16 < 2; ++k16) {
            const uint32_t koff = buf + k16*32;
            #pragma unroll
            for (int p = 0; p < 2; ++p) {
                uint32_t r[4];
                ldsm4(r, koff + b_off[p]);
                bh[k16][2*p][0]=r[0]; bh[k16][2*p][1]=r[2];
                bh[k16][2*p+1][0]=r[1]; bh[k16][2*p+1][1]=r[3];
                ldsm4(r, koff + b_off[p] + TILE_BYTES);
                bl[k16][2*p][0]=r[0]; bl[k16][2*p][1]=r[2];
                bl[k16][2*p+1][0]=r[1]; bl[k16][2*p+1][1]=r[3];
            }
        }
        #pragma unroll
        for (int k16 = 0; k16 < 2; ++k16) {
            const uint32_t koff = buf + k16*32;
            #pragma unroll
            for (int mf = 0; mf < 4; ++mf) {
                uint32_t ah[4], al[4];
                ldsm4(ah, koff + a_off[mf]);
                ldsm4(al, koff + a_off[mf] + TILE_BYTES);
                #pragma unroll
                for (int nf = 0; nf < 4; ++nf) {
                    mma16816(c[mf][nf], ah, bh[k16][nf]);
                    mma16816(c[mf][nf], ah, bl[k16][nf]);
                    mma16816(c[mf][nf], al, bh[k16][nf]);
                }
            }
        }
        __syncthreads();
        if (s + 2 < 32) ISSUE(s + 2);
    }

    const int tq = lane >> 2, tr = lane & 3;
    #pragma unroll
    for (int mf = 0; mf < 4; ++mf) {
        #pragma unroll
        for (int nf = 0; nf < 4; ++nf) {
            #pragma unroll
            for (int half = 0; half < 2; ++half) {
                const int m = bm + warp_m*64 + mf*16 + tq + half*8;
                const int n0 = bn + warp_n*32 + nf*8 + tr*2;
                float v0 = c[mf][nf][half*2 + 0] + bias[n0];
                float v1 = c[mf][nf][half*2 + 1] + bias[n0 + 1];
                const int bb = m >> 11, t = m & 2047;
                if (z <= 2) {
                    const int h = n0 >> 6, hd = n0 & 63;
                    float* dst = ((z==0) ? g_Q : (z==1) ? g_K : g_V)
                                 + (((size_t)(bb*H_ + h) * T_ + t) * HD_) + hd;
                    if (z <= 1) {
                        const float4 cs = g_rope[(size_t)t*32 + (hd >> 1)];
                        *(float2*)dst = make_float2(v0*cs.x - v1*cs.y, v1*cs.z + v0*cs.w);
                    } else {
                        *(float2*)dst = make_float2(v0, v1);
                    }
                } else if (z == 3) {
                    g_G[(size_t)m*E_ + n0]     = v0 / (1.f + __expf(-v0));
                    g_G[(size_t)m*E_ + n0 + 1] = v1 / (1.f + __expf(-v1));
                } else {
                    *(float2*)(Cout + (size_t)m*E_ + n0) = make_float2(v0, v1);
                }
            }
        }
    }
    #undef ISSUE
}

// ---------------- Pass 1a: per-chunk outer products U_c = sum_i gamma^i k_i v_i^T ----------------
// grid = (NT_-1, B_*H_): chunk cc = blockIdx.x+1 (U_0 unused). 256 threads.
__global__ __launch_bounds__(256) void ret_u_kernel()
{
    __shared__ float KT[64][64];   // KT[d][i] = K[i][d] * gamma^i
    __shared__ float Vs[64][64];

    const int cc = blockIdx.x + 1;
    const int bh = blockIdx.y, h = bh & 15;
    const int j0 = cc * 64;
    const float* dec = g_decay + h * T_;

    const float* Kg = g_K + (size_t)bh * T_ * HD_;
    const float* Vg = g_V + (size_t)bh * T_ * HD_;
    float* Ug = g_U + ((size_t)bh * NT_ + cc) * (HD_*HD_);

    const int tid = threadIdx.x;
    const int tx = tid & 15, ty = tid >> 4;
    const int lrow = tid >> 2, lseg = (tid & 3) * 16;

    {
        const float w = dec[lrow];
        float4 k4[4];
        const float4* ks = (const float4*)(Kg + (size_t)(j0+lrow)*64 + lseg);
        #pragma unroll
        for (int q = 0; q < 4; ++q) k4[q] = ks[q];
        #pragma unroll
        for (int q = 0; q < 4; ++q) {
            KT[lseg+q*4+0][lrow] = k4[q].x * w;
            KT[lseg+q*4+1][lrow] = k4[q].y * w;
            KT[lseg+q*4+2][lrow] = k4[q].z * w;
            KT[lseg+q*4+3][lrow] = k4[q].w * w;
        }
        const float4* vs = (const float4*)(Vg + (size_t)(j0+lrow)*64 + lseg);
        float4* vd = (float4*)(&Vs[lrow][lseg]);
        #pragma unroll
        for (int q = 0; q < 4; ++q) vd[q] = vs[q];
    }
    __syncthreads();

    float u[4][4];
    #pragma unroll
    for (int i = 0; i < 4; ++i)
        #pragma unroll
        for (int j = 0; j < 4; ++j) u[i][j] = 0.f;

    #pragma unroll 8
    for (int t = 0; t < 64; ++t) {
        float4 vv = *(const float4*)(&Vs[t][tx*4]);
        float kd[4];
        #pragma unroll
        for (int i = 0; i < 4; ++i) kd[i] = KT[ty*4+i][t];
        #pragma unroll
        for (int i = 0; i < 4; ++i) {
            u[i][0] = fmaf(kd[i], vv.x, u[i][0]); u[i][1] = fmaf(kd[i], vv.y, u[i][1]);
            u[i][2] = fmaf(kd[i], vv.z, u[i][2]); u[i][3] = fmaf(kd[i], vv.w, u[i][3]);
        }
    }
    #pragma unroll
    for (int i = 0; i < 4; ++i)
        *(float4*)&Ug[(ty*4+i)*64 + tx*4] = make_float4(u[i][0], u[i][1], u[i][2], u[i][3]);
}

// ---------------- Pass 1b: elementwise backward scan over chunks ----------------
// R_{31} = 0;  R_{cc-1} = U_cc + gamma^64 * R_cc   (per (bh,d,e) independent)
// 32768 float4-threads.
__global__ __launch_bounds__(256) void ret_scan_kernel()
{
    const int idx = blockIdx.x*256 + threadIdx.x;       // 0..32767
    const int bh = idx >> 10;
    const int de = (idx & 1023) * 4;                    // float4 offset within 64x64
    const float gL = g_decay[(bh & 15)*T_ + 64];

    float* Rg = g_R + (size_t)bh * NT_ * (HD_*HD_) + de;
    const float* Ug = g_U + (size_t)bh * NT_ * (HD_*HD_) + de;

    float4 R = make_float4(0.f, 0.f, 0.f, 0.f);
    *(float4*)(Rg + (NT_-1)*(HD_*HD_)) = R;
    #pragma unroll 4
    for (int cc = NT_-1; cc >= 1; --cc) {
        const float4 U = *(const float4*)(Ug + cc*(HD_*HD_));
        R.x = U.x + gL*R.x; R.y = U.y + gL*R.y;
        R.z = U.z + gL*R.z; R.w = U.w + gL*R.w;
        *(float4*)(Rg + (cc-1)*(HD_*HD_)) = R;
    }
}

// ---------------- Pass 2: intra-chunk + cross-chunk ----------------
__global__ __launch_bounds__(256) void ret_attn_kernel()
{
    __shared__ float Qs[64][64];
    __shared__ float KS[64][64];
    __shared__ float Vs[64][64];

    const int bh = blockIdx.y, b = bh >> 4, h = bh & 15;
    const int cI = blockIdx.x, q0 = cI * 64;

    const float* Qg = g_Q + (size_t)bh * T_ * HD_;
    const float* Kg = g_K + (size_t)bh * T_ * HD_;
    const float* Vg = g_V + (size_t)bh * T_ * HD_;
    const float* dec = g_decay + h * T_;
    const float* Rg = g_R + ((size_t)bh * NT_ + cI) * (HD_*HD_);

    const int tid = threadIdx.x;
    const int tx = tid & 15, ty = tid >> 4;
    const int lrow = tid >> 2, lseg = (tid & 3) * 16;

    {
        const float4* qsrc = (const float4*)(Qg + (size_t)(q0+lrow)*64 + lseg);
        float4* qdst = (float4*)(&Qs[lrow][lseg]);
        #pragma unroll
        for (int q = 0; q < 4; ++q) qdst[q] = qsrc[q];
        float4 k4[4];
        const float4* ks = (const float4*)(Kg + (size_t)(q0+lrow)*64 + lseg);
        #pragma unroll
        for (int q = 0; q < 4; ++q) k4[q] = ks[q];
        #pragma unroll
        for (int q = 0; q < 4; ++q) {
            KS[lseg+q*4+0][lrow] = k4[q].x; KS[lseg+q*4+1][lrow] = k4[q].y;
            KS[lseg+q*4+2][lrow] = k4[q].z; KS[lseg+q*4+3][lrow] = k4[q].w;
        }
        const float4* vs = (const float4*)(Vg + (size_t)(q0+lrow)*64 + lseg);
        float4* vd = (float4*)(&Vs[lrow][lseg]);
        #pragma unroll
        for (int q = 0; q < 4; ++q) vd[q] = vs[q];
    }
    __syncthreads();

    const float invsc = 0.125f;
    float s[4][4];
    #pragma unroll
    for (int i = 0; i < 4; ++i)
        #pragma unroll
        for (int j = 0; j < 4; ++j) s[i][j] = 0.f;

    #pragma unroll 8
    for (int k = 0; k < 64; ++k) {
        float4 kv = *(const float4*)(&KS[k][tx*4]);
        float qv[4];
        #pragma unroll
        for (int i = 0; i < 4; ++i) qv[i] = Qs[ty*4+i][k];
        #pragma unroll
        for (int i = 0; i < 4; ++i) {
            s[i][0] = fmaf(qv[i], kv.x, s[i][0]); s[i][1] = fmaf(qv[i], kv.y, s[i][1]);
            s[i][2] = fmaf(qv[i], kv.z, s[i][2]); s[i][3] = fmaf(qv[i], kv.w, s[i][3]);
        }
    }
    #pragma unroll
    for (int i = 0; i < 4; ++i) {
        const int ii = ty*4 + i;
        #pragma unroll
        for (int j = 0; j < 4; ++j) {
            const int jj = tx*4 + j;
            s[i][j] = (jj >= ii) ? s[i][j] * invsc * dec[jj-ii] : 0.f;
        }
    }
    __syncthreads();
    #pragma unroll
    for (int i = 0; i < 4; ++i)
        *(float4*)(&KS[ty*4+i][tx*4]) = make_float4(s[i][0], s[i][1], s[i][2], s[i][3]);
    __syncthreads();

    float o[4][4];
    #pragma unroll
    for (int i = 0; i < 4; ++i)
        #pragma unroll
        for (int j = 0; j < 4; ++j) o[i][j] = 0.f;

    #pragma unroll 8
    for (int k = 0; k < 64; ++k) {
        float4 vv = *(const float4*)(&Vs[k][tx*4]);
        float sv[4];
        #pragma unroll
        for (int i = 0; i < 4; ++i) sv[i] = KS[ty*4+i][k];
        #pragma unroll
        for (int i = 0; i < 4; ++i) {
            o[i][0] = fmaf(sv[i], vv.x, o[i][0]); o[i][1] = fmaf(sv[i], vv.y, o[i][1]);
            o[i][2] = fmaf(sv[i], vv.z, o[i][2]); o[i][3] = fmaf(sv[i], vv.w, o[i][3]);
        }
    }

    float cr[4][4];
    #pragma unroll
    for (int i = 0; i < 4; ++i)
        #pragma unroll
        for (int j = 0; j < 4; ++j) cr[i][j] = 0.f;
    #pragma unroll 4
    for (int d = 0; d < 64; ++d) {
        const float4 rv = __ldg((const float4*)&Rg[d*64 + tx*4]);
        float qd[4];
        #pragma unroll
        for (int i = 0; i < 4; ++i) qd[i] = Qs[ty*4+i][d];
        #pragma unroll
        for (int i = 0; i < 4; ++i) {
            cr[i][0] = fmaf(qd[i], rv.x, cr[i][0]); cr[i][1] = fmaf(qd[i], rv.y, cr[i][1]);
            cr[i][2] = fmaf(qd[i], rv.z, cr[i][2]); cr[i][3] = fmaf(qd[i], rv.w, cr[i][3]);
        }
    }
    #pragma unroll
    for (int i = 0; i < 4; ++i) {
        const int ii = ty*4 + i;
        const float coef = invsc * dec[64 - ii];
        #pragma unroll
        for (int j = 0; j < 4; ++j) o[i][j] = fmaf(coef, cr[i][j], o[i][j]);
    }
    #pragma unroll
    for (int i = 0; i < 4; ++i) {
        const int t = q0 + ty*4 + i;
        float* dst = g_O + ((size_t)(b*T_ + t)) * E_ + h*64 + tx*4;
        *(float4*)dst = make_float4(o[i][0], o[i][1], o[i][2], o[i][3]);
    }
}

// ---------------- GroupNorm stats ----------------
__global__ __launch_bounds__(256) void gn_stats_kernel()
{
    const int bh = blockIdx.x >> 3, slice = blockIdx.x & 7;
    const int b = bh >> 4, h = bh & 15;
    const size_t base = (size_t)b * T_ * E_ + h * 64;
    const int t0 = slice * (T_/8);

    float sum = 0.f, sumsq = 0.f;
    for (int i = threadIdx.x; i < (T_/8)*64; i += 256) {
        const int t = t0 + (i >> 6), hd = i & 63;
        const float v = g_O[base + (size_t)t * E_ + hd];
        sum += v; sumsq = fmaf(v, v, sumsq);
    }
    __shared__ float ssum[256], ssq[256];
    ssum[threadIdx.x] = sum; ssq[threadIdx.x] = sumsq;
    __syncthreads();
    for (int off = 128; off > 0; off >>= 1) {
        if (threadIdx.x < off) { ssum[threadIdx.x] += ssum[threadIdx.x+off]; ssq[threadIdx.x] += ssq[threadIdx.x+off]; }
        __syncthreads();
    }
    if (threadIdx.x == 0) {
        atomicAdd(&g_stat[bh].x, ssum[0]);
        atomicAdd(&g_stat[bh].y, ssq[0]);
    }
}

// ---------------- GroupNorm apply + gate -> bf16 split ----------------
__global__ __launch_bounds__(256) void gn_apply_kernel(
    const float* __restrict__ gn_w, const float* __restrict__ gn_b)
{
    const int i4 = blockIdx.x*256 + threadIdx.x;
    const size_t i = (size_t)i4 * 4;
    const int e0 = (int)(i & (E_-1));
    const int bt = (int)(i >> 10);
    const int bh = (bt >> 11) * H_ + (e0 >> 6);

    const float2 st = g_stat[bh];
    const float N = (float)(T_ * HD_);
    const float mu = st.x / N;
    const float rs = rsqrtf(st.y / N - mu*mu + 1e-5f);

    const float4 o = *(const float4*)(g_O + i);
    const float4 g = *(const float4*)(g_G + i);
    const float4 w = *(const float4*)(gn_w + e0);
    const float4 bb = *(const float4*)(gn_b + e0);

    float out[4];
    out[0] = ((o.x - mu) * rs * w.x + bb.x) * g.x;
    out[1] = ((o.y - mu) * rs * w.y + bb.y) * g.y;
    out[2] = ((o.z - mu) * rs * w.z + bb.z) * g.z;
    out[3] = ((o.w - mu) * rs * w.w + bb.w) * g.w;

    __nv_bfloat16 hi[4], lo[4];
    #pragma unroll
    for (int q = 0; q < 4; ++q) {
        hi[q] = __float2bfloat16(out[q]);
        lo[q] = __float2bfloat16(out[q] - __bfloat162float(hi[q]));
    }
    *(uint2*)(g_Ah + i) = *(uint2*)hi;
    *(uint2*)(g_Al + i) = *(uint2*)lo;
}

// ---------------- launch ----------------
extern "C" void kernel_launch(void* const* d_in, const int* in_sizes, int n_in,
                              void* d_out, int out_size)
{
    const float* x    = (const float*)d_in[0];
    const float* Wq   = (const float*)d_in[1];
    const float* bq   = (const float*)d_in[2];
    const float* Wk   = (const float*)d_in[3];
    const float* bk   = (const float*)d_in[4];
    const float* Wv   = (const float*)d_in[5];
    const float* bv   = (const float*)d_in[6];
    const float* Wg   = (const float*)d_in[7];
    const float* bg   = (const float*)d_in[8];
    const float* Wo   = (const float*)d_in[9];
    const float* bo   = (const float*)d_in[10];
    const float* gn_w = (const float*)d_in[11];
    const float* gn_b = (const float*)d_in[12];

    __nv_bfloat16 *Ah, *Al;
    cudaGetSymbolAddress((void**)&Ah, g_Ah);
    cudaGetSymbolAddress((void**)&Al, g_Al);

    cudaFuncSetAttribute(tc_gemm, cudaFuncAttributeMaxDynamicSharedMemorySize, DYN_SMEM);

    tables_kernel<<<(T_*32 + 255)/256, 256>>>();

    const int ntot = M_*E_ + 5*E_*E_;
    split_all_kernel<<<(ntot + 255)/256, 256>>>(x, Wq, Wk, Wv, Wg, Wo);

    tc_gemm<<<dim3(E_/128, M_/128, 4), 256, DYN_SMEM>>>(Ah, Al, bq, bk, bv, bg, nullptr, -1);

    ret_u_kernel<<<dim3(NT_-1, B_*H_), 256>>>();
    ret_scan_kernel<<<128, 256>>>();
    ret_attn_kernel<<<dim3(NT_, B_*H_), 256>>>();

    gn_stats_kernel<<<B_*H_*8, 256>>>();
    gn_apply_kernel<<<(M_*E_/4 + 255)/256, 256>>>(gn_w, gn_b);

    tc_gemm<<<dim3(E_/128, M_/128, 1), 256, DYN_SMEM>>>(Ah, Al, bo, nullptr, nullptr, nullptr,
                                                        (float*)d_out, 4);
}